// round 12
// baseline (speedup 1.0000x reference)
#include <cuda_runtime.h>
#include <cuda_bf16.h>
#include <cuda_fp16.h>
#include <math.h>
#include <stdint.h>

#define ALPHA 1.3f
#define GNEPS 1e-5f
// B=64, M=1024, D=1024, H=8, HD=128

// ---------------- scratch (__device__ globals) -------------------------------
__device__ float g_qbuf[64 * 1024];
__device__ float g_v1buf[64 * 1024];
__device__ float g_dotb[64 * 8 * 1024];
__device__ float g_knb[64 * 8 * 1024];
__device__ __half g_v2h[67108864];             // v2 projected fp16

// Pre-converted W^T tiles: [mode][ (h*64+kc)*128 + n ]*24 + k  (k16 chunks, pad 24)
// mode 0 holds fp16 bits (single precision pass); mode 1 holds bf16 hi (+lo below)
__device__ __nv_bfloat16 g_Bhi[2][1572864];
__device__ __nv_bfloat16 g_Blo[2][1572864];    // only [1] used

__device__ __forceinline__ float celu_f(float x) {
    return x > 0.f ? x : ALPHA * expm1f(x * (1.0f / ALPHA));
}

// ---------------- PTX helpers ------------------------------------------------
__device__ __forceinline__ uint32_t smem_u32(const void* p) {
    return (uint32_t)__cvta_generic_to_shared(p);
}
__device__ __forceinline__ void cp16(uint32_t dst, const void* src) {
    asm volatile("cp.async.cg.shared.global [%0], [%1], 16;\n"
                 :: "r"(dst), "l"(__cvta_generic_to_global(src)));
}
#define CP_COMMIT()  asm volatile("cp.async.commit_group;\n" ::: "memory")
#define CP_WAIT1()   asm volatile("cp.async.wait_group 1;\n" ::: "memory")
#define CP_WAIT0()   asm volatile("cp.async.wait_group 0;\n" ::: "memory")

__device__ __forceinline__ void ldsm4(uint32_t* d, uint32_t addr) {
    asm volatile("ldmatrix.sync.aligned.m8n8.x4.shared.b16 {%0,%1,%2,%3}, [%4];"
                 : "=r"(d[0]), "=r"(d[1]), "=r"(d[2]), "=r"(d[3]) : "r"(addr));
}
__device__ __forceinline__ void mma16816(float* c, const uint32_t* a,
                                         uint32_t b0, uint32_t b1) {
    asm volatile(
        "mma.sync.aligned.m16n8k16.row.col.f32.bf16.bf16.f32 "
        "{%0,%1,%2,%3}, {%4,%5,%6,%7}, {%8,%9}, {%0,%1,%2,%3};"
        : "+f"(c[0]), "+f"(c[1]), "+f"(c[2]), "+f"(c[3])
        : "r"(a[0]), "r"(a[1]), "r"(a[2]), "r"(a[3]), "r"(b0), "r"(b1));
}
__device__ __forceinline__ void mma16816h(float* c, const uint32_t* a,
                                          uint32_t b0, uint32_t b1) {
    asm volatile(
        "mma.sync.aligned.m16n8k16.row.col.f32.f16.f16.f32 "
        "{%0,%1,%2,%3}, {%4,%5,%6,%7}, {%8,%9}, {%0,%1,%2,%3};"
        : "+f"(c[0]), "+f"(c[1]), "+f"(c[2]), "+f"(c[3])
        : "r"(a[0]), "r"(a[1]), "r"(a[2]), "r"(a[3]), "r"(b0), "r"(b1));
}
__device__ __forceinline__ float quad2(float v) {
    v += __shfl_xor_sync(0xffffffffu, v, 1);
    v += __shfl_xor_sync(0xffffffffu, v, 2);
    return v;
}
__device__ __forceinline__ uint4 pack_hi8(const float* v, float* rem) {
    __nv_bfloat16 h[8];
#pragma unroll
    for (int i = 0; i < 8; i++) {
        h[i] = __float2bfloat16(v[i]);
        rem[i] = v[i] - __bfloat162float(h[i]);
    }
    uint4 r;
    __nv_bfloat162 p;
    p.x = h[0]; p.y = h[1]; r.x = *(uint32_t*)&p;
    p.x = h[2]; p.y = h[3]; r.y = *(uint32_t*)&p;
    p.x = h[4]; p.y = h[5]; r.z = *(uint32_t*)&p;
    p.x = h[6]; p.y = h[7]; r.w = *(uint32_t*)&p;
    return r;
}
__device__ __forceinline__ uint4 pack8(const float* v) {
    uint4 r;
    __nv_bfloat162 p;
    p.x = __float2bfloat16(v[0]); p.y = __float2bfloat16(v[1]); r.x = *(uint32_t*)&p;
    p.x = __float2bfloat16(v[2]); p.y = __float2bfloat16(v[3]); r.y = *(uint32_t*)&p;
    p.x = __float2bfloat16(v[4]); p.y = __float2bfloat16(v[5]); r.z = *(uint32_t*)&p;
    p.x = __float2bfloat16(v[6]); p.y = __float2bfloat16(v[7]); r.w = *(uint32_t*)&p;
    return r;
}
__device__ __forceinline__ uint4 pack8_f16(const float* v) {
    uint4 r;
    __half2 p;
    p = __floats2half2_rn(v[0], v[1]); r.x = *(uint32_t*)&p;
    p = __floats2half2_rn(v[2], v[3]); r.y = *(uint32_t*)&p;
    p = __floats2half2_rn(v[4], v[5]); r.z = *(uint32_t*)&p;
    p = __floats2half2_rn(v[6], v[7]); r.w = *(uint32_t*)&p;
    return r;
}

// ---------------- convB: W -> per-head [n][k] tiles --------------------------
// grid (64 kc, 8 head, 2 mode), 256 threads.
// mode 0: fp16 single (g_Bhi[0] holds fp16 bits). mode 1: bf16 hi/lo.
__global__ __launch_bounds__(256) void convB_kernel(
    const float* __restrict__ W_k, const float* __restrict__ W_v2)
{
    const int kc = blockIdx.x, h = blockIdx.y, mode = blockIdx.z, tid = threadIdx.x;
    const float* W = mode ? W_v2 : W_k;
    const int n = tid & 127;
    const int kh = (tid >> 7) * 8;
    float vals[8], rem[8];
#pragma unroll
    for (int j = 0; j < 8; j++)
        vals[j] = W[(size_t)(kc * 16 + kh + j) * 1024 + h * 128 + n];
    const size_t base = ((size_t)(h * 64 + kc) * 128 + n) * 24 + kh;
    if (mode == 0) {
        *(uint4*)&g_Bhi[0][base] = pack8_f16(vals);
    } else {
        const uint4 hi = pack_hi8(vals, rem);
        const uint4 lo = pack8(rem);
        *(uint4*)&g_Bhi[1][base] = hi;
        *(uint4*)&g_Blo[1][base] = lo;
    }
}

// ---------------- small projections: q + v1 merged (grid.y = 2) --------------
__global__ __launch_bounds__(512) void small_proj_kernel(
    const float* __restrict__ Xq, const float* __restrict__ Wq,
    const float* __restrict__ bq, const float* __restrict__ gq, const float* __restrict__ betq,
    const float* __restrict__ Xv, const float* __restrict__ Wv,
    const float* __restrict__ bv, const float* __restrict__ gv, const float* __restrict__ betv)
{
    __shared__ float xs[1024];
    __shared__ float part[4][128];
    __shared__ float sh[16];
    const int row = blockIdx.x >> 3;
    const int h   = blockIdx.x & 7;
    const int dst = blockIdx.y;
    const int tid = threadIdx.x;
    const int c   = tid & 127;
    const int kq  = tid >> 7;

    const float* X     = dst ? Xv   : Xq;
    const float* W     = dst ? Wv   : Wq;
    const float* bias  = dst ? bv   : bq;
    const float* gw    = dst ? gv   : gq;
    const float* betaw = dst ? betv : betq;

    if (tid < 256)
        ((float4*)xs)[tid] = ((const float4*)(X + (size_t)row * 1024))[tid];
    __syncthreads();

    const int col = h * 128 + c;
    const float* Wp = W + (size_t)(kq * 256) * 1024 + col;
    const float* xp = xs + kq * 256;
    float a = 0.f;
#pragma unroll 16
    for (int k = 0; k < 256; k++) a = fmaf(xp[k], Wp[(size_t)k * 1024], a);
    part[kq][c] = a;
    __syncthreads();

    float acc = 0.f;
    if (tid < 128)
        acc = celu_f(part[0][c] + part[1][c] + part[2][c] + part[3][c] + bias[col]);

    float s = acc, s2 = acc * acc;
#pragma unroll
    for (int o = 16; o; o >>= 1) {
        s  += __shfl_xor_sync(0xffffffffu, s,  o);
        s2 += __shfl_xor_sync(0xffffffffu, s2, o);
    }
    if ((tid & 31) == 0) { sh[tid >> 5] = s; sh[(tid >> 5) + 8] = s2; }
    __syncthreads();
    if (tid < 128) {
        s  = sh[0] + sh[1] + sh[2]  + sh[3];
        s2 = sh[8] + sh[9] + sh[10] + sh[11];
        const float mu   = s * (1.f / 128.f);
        const float rstd = rsqrtf(s2 * (1.f / 128.f) - mu * mu + GNEPS);
        const float v = (acc - mu) * rstd * gw[col] + betaw[col];
        if (dst == 0) g_qbuf[row * 1024 + col] = v;
        else          g_v1buf[row * 1024 + col] = v;
    }
}

// ---------------- merged tensor-core big projection GEMM ---------------------
// grid (8 heads, 512 row-tiles, 2 modes), 256 thr = 8 warps (4M x 2N).
// mode 0 (key): SINGLE-PASS fp16 mma. mode 1 (value2): 3-pass bf16 (proven).
__global__ __launch_bounds__(256, 2) void big_mma_kernel(
    const float* __restrict__ key,  const float* __restrict__ value2,
    const float* __restrict__ b_k,  const float* __restrict__ g_k,  const float* __restrict__ beta_k,
    const float* __restrict__ b_v,  const float* __restrict__ g_v,  const float* __restrict__ beta_v)
{
    __shared__ __align__(16) __nv_bfloat16 sAhi[128][24];
    __shared__ __align__(16) __nv_bfloat16 sAlo[128][24];
    __shared__ __align__(16) __nv_bfloat16 sB[2][2][128][24];
    __shared__ float sbias[128], sg[128], sbeta[128], sq[128];
    __shared__ float psum[128][2], psum2[128][2];
    __shared__ float pdot[128][2], pk2[128][2];

    const int h    = blockIdx.x;
    const int tm   = blockIdx.y;
    const int mode = blockIdx.z;
    const int tid  = threadIdx.x;
    const int lane = tid & 31;
    const int warp = tid >> 5;
    const int wm   = warp >> 1;
    const int wn   = warp & 1;
    const int col0 = h * 128;
    const int b0   = tm >> 3;

    const float* A     = mode ? value2 : key;
    const float* bias  = mode ? b_v    : b_k;
    const float* gw    = mode ? g_v    : g_k;
    const float* betaw = mode ? beta_v : beta_k;

    if (tid < 128) {
        sbias[tid] = bias[col0 + tid];
        sg[tid]    = gw[col0 + tid];
        sbeta[tid] = betaw[col0 + tid];
        sq[tid]    = (mode == 0) ? g_qbuf[b0 * 1024 + col0 + tid] : 0.f;
    }

    const int ar = tid >> 1;
    const int ak = (tid & 1) * 8;
    const float* Abase = A + (size_t)(tm * 128 + ar) * 1024 + ak;

    float pf[8];
    auto ldgA = [&](int kc) {
        const float4* p = (const float4*)(Abase + kc * 16);
        *(float4*)&pf[0] = p[0];
        *(float4*)&pf[4] = p[1];
    };
    const uint32_t aHiRow = smem_u32(&sAhi[ar][ak]);
    const uint32_t aLoRow = smem_u32(&sAlo[ar][ak]);

    const __nv_bfloat16* Bhi = g_Bhi[mode];
    const __nv_bfloat16* Blo = g_Blo[1];
    const uint32_t sB0 = smem_u32(&sB[0][0][0][0]);

    const uint32_t aHi = smem_u32(sAhi), aLo = smem_u32(sAlo);
    const uint32_t klane = (uint32_t)(((lane >> 4) & 1) * 16);
    uint32_t aoff[2];
#pragma unroll
    for (int mt = 0; mt < 2; mt++) {
        const int r = wm * 32 + mt * 16 + (lane & 7) + 8 * ((lane >> 3) & 1);
        aoff[mt] = (uint32_t)r * 48u + klane;
    }
    uint32_t boff[4];
#pragma unroll
    for (int bp = 0; bp < 4; bp++) {
        const int n = wn * 64 + bp * 16 + (lane & 7) + 8 * ((lane >> 3) & 1);
        boff[bp] = (uint32_t)n * 48u + klane;
    }

    float acc[2][8][4];
#pragma unroll
    for (int mt = 0; mt < 2; mt++)
#pragma unroll
        for (int nf = 0; nf < 8; nf++)
#pragma unroll
            for (int q = 0; q < 4; q++) acc[mt][nf][q] = 0.f;

    if (mode == 0) {
        // ---- single-pass fp16 mainloop ----
        auto cpB0 = [&](int kc, int stg) {
            const size_t tb = (size_t)(h * 64 + kc) * 3072;
            const uint32_t d = sB0 + (uint32_t)stg * 12288u;
            cp16(d + (uint32_t)tid * 16u, Bhi + tb + (size_t)tid * 8);
            if (tid < 128) cp16(d + (uint32_t)(tid + 256) * 16u, Bhi + tb + (size_t)(tid + 256) * 8);
        };
        ldgA(0);
        cpB0(0, 0);
        CP_COMMIT();
        for (int kc = 0; kc < 64; kc++) {
            *(uint4*)__cvta_shared_to_generic(aHiRow) = pack8_f16(pf);
            if (kc < 63) { cpB0(kc + 1, (kc + 1) & 1); CP_COMMIT(); CP_WAIT1(); }
            else         { CP_WAIT0(); }
            __syncthreads();
            if (kc < 63) ldgA(kc + 1);

            const uint32_t bbase = sB0 + (uint32_t)(kc & 1) * 12288u;
            uint32_t ah[2][4];
#pragma unroll
            for (int mt = 0; mt < 2; mt++) ldsm4(ah[mt], aHi + aoff[mt]);
#pragma unroll
            for (int bp = 0; bp < 4; bp++) {
                uint32_t bh[4];
                ldsm4(bh, bbase + boff[bp]);
#pragma unroll
                for (int mt = 0; mt < 2; mt++) {
                    mma16816h(acc[mt][2 * bp],     ah[mt], bh[0], bh[2]);
                    mma16816h(acc[mt][2 * bp + 1], ah[mt], bh[1], bh[3]);
                }
            }
            __syncthreads();
        }
    } else {
        // ---- 3-pass bf16 mainloop (R10 proven, verbatim) ----
        auto storeA = [&]() {
            float rem[8];
            const uint4 hi = pack_hi8(pf, rem);
            const uint4 lo = pack8(rem);
            *(uint4*)__cvta_shared_to_generic(aHiRow) = hi;
            *(uint4*)__cvta_shared_to_generic(aLoRow) = lo;
        };
        auto cpB = [&](int kc, int stg) {
            const size_t tb = (size_t)(h * 64 + kc) * 3072;
            const uint32_t d = sB0 + (uint32_t)stg * 12288u;
            cp16(d + (uint32_t)tid * 16u, Bhi + tb + (size_t)tid * 8);
            if (tid < 128) cp16(d + (uint32_t)(tid + 256) * 16u, Bhi + tb + (size_t)(tid + 256) * 8);
            cp16(d + 6144u + (uint32_t)tid * 16u, Blo + tb + (size_t)tid * 8);
            if (tid < 128) cp16(d + 6144u + (uint32_t)(tid + 256) * 16u, Blo + tb + (size_t)(tid + 256) * 8);
        };
        ldgA(0);
        cpB(0, 0);
        CP_COMMIT();
        for (int kc = 0; kc < 64; kc++) {
            storeA();
            if (kc < 63) { cpB(kc + 1, (kc + 1) & 1); CP_COMMIT(); CP_WAIT1(); }
            else         { CP_WAIT0(); }
            __syncthreads();
            if (kc < 63) ldgA(kc + 1);

            const uint32_t bbase = sB0 + (uint32_t)(kc & 1) * 12288u;
            uint32_t ah[2][4], al[2][4];
#pragma unroll
            for (int mt = 0; mt < 2; mt++) {
                ldsm4(ah[mt], aHi + aoff[mt]);
                ldsm4(al[mt], aLo + aoff[mt]);
            }
#pragma unroll
            for (int bp = 0; bp < 4; bp++) {
                uint32_t bh[4], bl[4];
                ldsm4(bh, bbase + boff[bp]);
                ldsm4(bl, bbase + 6144u + boff[bp]);
#pragma unroll
                for (int mt = 0; mt < 2; mt++) {
                    mma16816(acc[mt][2 * bp],     ah[mt], bh[0], bh[2]);
                    mma16816(acc[mt][2 * bp + 1], ah[mt], bh[1], bh[3]);
                    mma16816(acc[mt][2 * bp],     ah[mt], bl[0], bl[2]);
                    mma16816(acc[mt][2 * bp + 1], ah[mt], bl[1], bl[3]);
                    mma16816(acc[mt][2 * bp],     al[mt], bh[0], bh[2]);
                    mma16816(acc[mt][2 * bp + 1], al[mt], bh[1], bh[3]);
                }
            }
            __syncthreads();
        }
    }

    // ---- register epilogue (proven) ----
    const int bh2 = b0 * 8 + h;
#pragma unroll
    for (int mt = 0; mt < 2; mt++)
#pragma unroll
        for (int nf = 0; nf < 8; nf++) {
            const int c = wn * 64 + nf * 8 + 2 * (lane & 3);
            acc[mt][nf][0] = celu_f(acc[mt][nf][0] + sbias[c]);
            acc[mt][nf][1] = celu_f(acc[mt][nf][1] + sbias[c + 1]);
            acc[mt][nf][2] = celu_f(acc[mt][nf][2] + sbias[c]);
            acc[mt][nf][3] = celu_f(acc[mt][nf][3] + sbias[c + 1]);
        }

#pragma unroll
    for (int mt = 0; mt < 2; mt++) {
        float sA = 0.f, s2A = 0.f, sBv = 0.f, s2B = 0.f;
#pragma unroll
        for (int nf = 0; nf < 8; nf++) {
            sA += acc[mt][nf][0] + acc[mt][nf][1];
            s2A = fmaf(acc[mt][nf][0], acc[mt][nf][0], fmaf(acc[mt][nf][1], acc[mt][nf][1], s2A));
            sBv += acc[mt][nf][2] + acc[mt][nf][3];
            s2B = fmaf(acc[mt][nf][2], acc[mt][nf][2], fmaf(acc[mt][nf][3], acc[mt][nf][3], s2B));
        }
        sA = quad2(sA); s2A = quad2(s2A); sBv = quad2(sBv); s2B = quad2(s2B);
        if ((lane & 3) == 0) {
            const int R = wm * 32 + mt * 16 + (lane >> 2);
            psum[R][wn] = sA;       psum2[R][wn] = s2A;
            psum[R + 8][wn] = sBv;  psum2[R + 8][wn] = s2B;
        }
    }
    __syncthreads();

    float mu_[2][2], rs_[2][2];
#pragma unroll
    for (int mt = 0; mt < 2; mt++)
#pragma unroll
        for (int hf = 0; hf < 2; hf++) {
            const int R = wm * 32 + mt * 16 + (lane >> 2) + 8 * hf;
            const float S  = psum[R][0] + psum[R][1];
            const float S2 = psum2[R][0] + psum2[R][1];
            const float mu = S * (1.f / 128.f);
            mu_[mt][hf] = mu;
            rs_[mt][hf] = rsqrtf(S2 * (1.f / 128.f) - mu * mu + GNEPS);
        }

    if (mode == 0) {
#pragma unroll
        for (int mt = 0; mt < 2; mt++) {
            float dpA = 0.f, k2A = 0.f, dpB = 0.f, k2B = 0.f;
#pragma unroll
            for (int nf = 0; nf < 8; nf++) {
                const int c = wn * 64 + nf * 8 + 2 * (lane & 3);
                float v0 = (acc[mt][nf][0] - mu_[mt][0]) * rs_[mt][0] * sg[c]     + sbeta[c];
                float v1 = (acc[mt][nf][1] - mu_[mt][0]) * rs_[mt][0] * sg[c + 1] + sbeta[c + 1];
                float v2 = (acc[mt][nf][2] - mu_[mt][1]) * rs_[mt][1] * sg[c]     + sbeta[c];
                float v3 = (acc[mt][nf][3] - mu_[mt][1]) * rs_[mt][1] * sg[c + 1] + sbeta[c + 1];
                dpA = fmaf(v0, sq[c], fmaf(v1, sq[c + 1], dpA));
                k2A = fmaf(v0, v0, fmaf(v1, v1, k2A));
                dpB = fmaf(v2, sq[c], fmaf(v3, sq[c + 1], dpB));
                k2B = fmaf(v2, v2, fmaf(v3, v3, k2B));
            }
            dpA = quad2(dpA); k2A = quad2(k2A); dpB = quad2(dpB); k2B = quad2(k2B);
            if ((lane & 3) == 0) {
                const int R = wm * 32 + mt * 16 + (lane >> 2);
                pdot[R][wn] = dpA;      pk2[R][wn] = k2A;
                pdot[R + 8][wn] = dpB;  pk2[R + 8][wn] = k2B;
            }
        }
        __syncthreads();
        if (wn == 0 && (lane & 3) == 0) {
#pragma unroll
            for (int mt = 0; mt < 2; mt++)
#pragma unroll
                for (int hf = 0; hf < 2; hf++) {
                    const int R = wm * 32 + mt * 16 + (lane >> 2) + 8 * hf;
                    const int m = (tm * 128 + R) & 1023;
                    g_dotb[bh2 * 1024 + m] = pdot[R][0] + pdot[R][1];
                    g_knb[bh2 * 1024 + m]  = sqrtf(pk2[R][0] + pk2[R][1]);
                }
        }
    } else {
#pragma unroll
        for (int mt = 0; mt < 2; mt++)
#pragma unroll
            for (int hf = 0; hf < 2; hf++) {
                const int R = wm * 32 + mt * 16 + (lane >> 2) + 8 * hf;
                const int m = (tm * 128 + R) & 1023;
                __half* dst = g_v2h + ((size_t)bh2 * 1024 + m) * 128;
                const float mu = mu_[mt][hf], rstd = rs_[mt][hf];
#pragma unroll
                for (int nf = 0; nf < 8; nf++) {
                    const int c = wn * 64 + nf * 8 + 2 * (lane & 3);
                    const float v0 = (acc[mt][nf][2 * hf]     - mu) * rstd * sg[c]     + sbeta[c];
                    const float v1 = (acc[mt][nf][2 * hf + 1] - mu) * rstd * sg[c + 1] + sbeta[c + 1];
                    *(__half2*)(dst + c) = __floats2half2_rn(v0, v1);
                }
            }
    }
}

// ---------------- attention / pooling / output (256 threads) -----------------
__device__ __forceinline__ float bsum256(float v, float* sh) {
#pragma unroll
    for (int o = 16; o; o >>= 1) v += __shfl_xor_sync(0xffffffffu, v, o);
    if ((threadIdx.x & 31) == 0) sh[threadIdx.x >> 5] = v;
    __syncthreads();
    v = (sh[0] + sh[1]) + (sh[2] + sh[3]) + ((sh[4] + sh[5]) + (sh[6] + sh[7]));
    __syncthreads();
    return v;
}
__device__ __forceinline__ float bmax256(float v, float* sh) {
#pragma unroll
    for (int o = 16; o; o >>= 1) v = fmaxf(v, __shfl_xor_sync(0xffffffffu, v, o));
    if ((threadIdx.x & 31) == 0) sh[threadIdx.x >> 5] = v;
    __syncthreads();
    v = fmaxf(fmaxf(fmaxf(sh[0], sh[1]), fmaxf(sh[2], sh[3])),
              fmaxf(fmaxf(sh[4], sh[5]), fmaxf(sh[6], sh[7])));
    __syncthreads();
    return v;
}

__global__ __launch_bounds__(256) void attn_kernel(
    const float* __restrict__ mask,
    const float* __restrict__ W1,  const float* __restrict__ b1,
    const float* __restrict__ Wl,  const float* __restrict__ bl,
    const float* __restrict__ Wl2, const float* __restrict__ bl2,
    float* __restrict__ out)
{
    __shared__ float qdir[128], u[64], b1s[64], wls[64], pool[64];
    __shared__ float cosv[1024], aspv[1024], maskv[1024];
    __shared__ float pp[4][64];
    __shared__ float vo[4][128];
    __shared__ float sh[8];

    const int bh  = blockIdx.x;
    const int b   = bh >> 3;
    const int tid = threadIdx.x;

    const float qv = (tid < 128) ? g_qbuf[bh * 128 + tid] : 0.f;
    const float qn = sqrtf(bsum256(qv * qv, sh));
    if (tid < 128) qdir[tid] = qv / fmaxf(qn, 1e-12f);
    if (tid < 64) { b1s[tid] = b1[tid]; wls[tid] = Wl[tid]; }
    __syncthreads();

    if (tid < 64) {
        float a = 0.f;
#pragma unroll 4
        for (int d = 0; d < 128; d++) a = fmaf(qdir[d], W1[d * 64 + tid], a);
        u[tid] = a;
    }
    __syncthreads();

    const float qnc = fmaxf(qn, 1e-8f);
    const float bl0 = bl[0];

    float lmax = -1e30f, msum = 0.f;
#pragma unroll
    for (int mi = 0; mi < 4; mi++) {
        const int m = tid + mi * 256;
        const float kn = g_knb[bh * 1024 + m];
        const float cs = g_dotb[bh * 1024 + m] / (qnc * fmaxf(kn, 1e-8f));
        cosv[m] = cs;
        const float mk = mask[b * 1024 + m];
        maskv[m] = mk;
        msum += mk;
        float lg = bl0;
#pragma unroll 8
        for (int j = 0; j < 64; j++)
            lg = fmaf(fmaxf(fmaf(cs, u[j], b1s[j]), 0.f), wls[j], lg);
        if (mk == 0.f) lg = -1e9f;
        aspv[m] = lg;
        lmax = fmaxf(lmax, lg);
    }
    lmax = bmax256(lmax, sh);
    msum = bsum256(msum, sh);

    float esum = 0.f;
#pragma unroll
    for (int mi = 0; mi < 4; mi++) {
        const int m = tid + mi * 256;
        const float e = expf(aspv[m] - lmax);
        aspv[m] = e;
        esum += e;
    }
    esum = bsum256(esum, sh);
    const float inv = 1.f / esum;
    __syncthreads();

    {
        const int j = tid & 63, qtr = tid >> 6;
        const float uj = u[j], bj = b1s[j];
        float p = 0.f;
        const int m0 = qtr * 256;
#pragma unroll 8
        for (int m = m0; m < m0 + 256; m++)
            p = fmaf(fmaxf(fmaf(cosv[m], uj, bj), 0.f), maskv[m], p);
        pp[qtr][j] = p;
    }
    __syncthreads();
    if (tid < 64)
        pool[tid] = (pp[0][tid] + pp[1][tid] + pp[2][tid] + pp[3][tid]) / msum;
    __syncthreads();

    {
        const int cc = (tid & 63) * 2, qtr = tid >> 6;
        const __half2* vb = (const __half2*)(g_v2h + (size_t)bh * 131072
                                             + (size_t)(qtr * 256) * 128 + cc);
        const float* av = aspv + qtr * 256;
        float ax = 0.f, ay = 0.f;
#pragma unroll 8
        for (int m = 0; m < 256; m++) {
            const float2 hv = __half22float2(vb[(size_t)m * 64]);
            const float w = av[m];
            ax = fmaf(w, hv.x, ax);
            ay = fmaf(w, hv.y, ay);
        }
        vo[qtr][cc] = ax;
        vo[qtr][cc + 1] = ay;
    }
    __syncthreads();

    if (tid < 128) {
        float a2 = bl2[tid];
#pragma unroll 8
        for (int j = 0; j < 64; j++) a2 = fmaf(pool[j], Wl2[j * 128 + tid], a2);
        const float ach = 1.f / (1.f + expf(-a2));
        const float v2o = (vo[0][tid] + vo[1][tid] + vo[2][tid] + vo[3][tid]) * inv;
        out[bh * 128 + tid] = g_v1buf[bh * 128 + tid] * v2o * ach;
    }
}

// ---------------- launch ------------------------------------------------------
extern "C" void kernel_launch(void* const* d_in, const int* in_sizes, int n_in,
                              void* d_out, int out_size) {
    const float* query   = (const float*)d_in[0];
    const float* key     = (const float*)d_in[1];
    const float* mask    = (const float*)d_in[2];
    const float* value1  = (const float*)d_in[3];
    const float* value2  = (const float*)d_in[4];
    const float* W_q     = (const float*)d_in[5];
    const float* b_q     = (const float*)d_in[6];
    const float* g_q     = (const float*)d_in[7];
    const float* beta_q  = (const float*)d_in[8];
    const float* W_k     = (const float*)d_in[9];
    const float* b_k     = (const float*)d_in[10];
    const float* g_k     = (const float*)d_in[11];
    const float* beta_k  = (const float*)d_in[12];
    const float* W_v1    = (const float*)d_in[13];
    const float* b_v1    = (const float*)d_in[14];
    const float* g_v1    = (const float*)d_in[15];
    const float* beta_v1 = (const float*)d_in[16];
    const float* W_v2    = (const float*)d_in[17];
    const float* b_v2    = (const float*)d_in[18];
    const float* g_v2    = (const float*)d_in[19];
    const float* beta_v2 = (const float*)d_in[20];
    const float* W1      = (const float*)d_in[21];
    const float* b1      = (const float*)d_in[22];
    const float* Wl      = (const float*)d_in[23];
    const float* bl      = (const float*)d_in[24];
    const float* Wl2     = (const float*)d_in[25];
    const float* bl2     = (const float*)d_in[26];
    float* out = (float*)d_out;

    convB_kernel<<<dim3(64, 8, 2), 256>>>(W_k, W_v2);

    small_proj_kernel<<<dim3(512, 2), 512>>>(query,  W_q,  b_q,  g_q,  beta_q,
                                             value1, W_v1, b_v1, g_v1, beta_v1);

    big_mma_kernel<<<dim3(8, 512, 2), 256>>>(key, value2,
                                             b_k,  g_k,  beta_k,
                                             b_v2, g_v2, beta_v2);

    attn_kernel<<<512, 256>>>(mask, W1, b1, Wl, bl, Wl2, bl2, out);
}

// round 13
// speedup vs baseline: 1.1373x; 1.1373x over previous
#include <cuda_runtime.h>
#include <cuda_bf16.h>
#include <cuda_fp16.h>
#include <math.h>
#include <stdint.h>

#define ALPHA 1.3f
#define GNEPS 1e-5f
// B=64, M=1024, D=1024, H=8, HD=128

// ---------------- scratch (__device__ globals) -------------------------------
__device__ float g_qbuf[64 * 1024];
__device__ float g_v1buf[64 * 1024];
__device__ float g_dotb[64 * 8 * 1024];
__device__ float g_knb[64 * 8 * 1024];
__device__ __half g_v2h[67108864];             // v2 projected fp16

// Pre-converted W^T tiles (fp16 bits): [mode][ (h*64+kc)*128 + n ]*24 + k
__device__ __half g_Bf[2][1572864];

__device__ __forceinline__ float celu_f(float x) {
    return x > 0.f ? x : ALPHA * expm1f(x * (1.0f / ALPHA));
}

// ---------------- PTX helpers ------------------------------------------------
__device__ __forceinline__ uint32_t smem_u32(const void* p) {
    return (uint32_t)__cvta_generic_to_shared(p);
}
__device__ __forceinline__ void cp16(uint32_t dst, const void* src) {
    asm volatile("cp.async.cg.shared.global [%0], [%1], 16;\n"
                 :: "r"(dst), "l"(__cvta_generic_to_global(src)));
}
#define CP_COMMIT()  asm volatile("cp.async.commit_group;\n" ::: "memory")
#define CP_WAIT1()   asm volatile("cp.async.wait_group 1;\n" ::: "memory")
#define CP_WAIT0()   asm volatile("cp.async.wait_group 0;\n" ::: "memory")

__device__ __forceinline__ void ldsm4(uint32_t* d, uint32_t addr) {
    asm volatile("ldmatrix.sync.aligned.m8n8.x4.shared.b16 {%0,%1,%2,%3}, [%4];"
                 : "=r"(d[0]), "=r"(d[1]), "=r"(d[2]), "=r"(d[3]) : "r"(addr));
}
__device__ __forceinline__ void mma16816h(float* c, const uint32_t* a,
                                          uint32_t b0, uint32_t b1) {
    asm volatile(
        "mma.sync.aligned.m16n8k16.row.col.f32.f16.f16.f32 "
        "{%0,%1,%2,%3}, {%4,%5,%6,%7}, {%8,%9}, {%0,%1,%2,%3};"
        : "+f"(c[0]), "+f"(c[1]), "+f"(c[2]), "+f"(c[3])
        : "r"(a[0]), "r"(a[1]), "r"(a[2]), "r"(a[3]), "r"(b0), "r"(b1));
}
__device__ __forceinline__ float quad2(float v) {
    v += __shfl_xor_sync(0xffffffffu, v, 1);
    v += __shfl_xor_sync(0xffffffffu, v, 2);
    return v;
}
__device__ __forceinline__ uint4 pack8_f16(const float* v) {
    uint4 r;
    __half2 p;
    p = __floats2half2_rn(v[0], v[1]); r.x = *(uint32_t*)&p;
    p = __floats2half2_rn(v[2], v[3]); r.y = *(uint32_t*)&p;
    p = __floats2half2_rn(v[4], v[5]); r.z = *(uint32_t*)&p;
    p = __floats2half2_rn(v[6], v[7]); r.w = *(uint32_t*)&p;
    return r;
}
__device__ __forceinline__ uint4 pack_hi8_f16(const float* v, float* rem) {
    __half h[8];
#pragma unroll
    for (int i = 0; i < 8; i++) {
        h[i] = __float2half_rn(v[i]);
        rem[i] = v[i] - __half2float(h[i]);
    }
    uint4 r;
    __half2 p;
    p.x = h[0]; p.y = h[1]; r.x = *(uint32_t*)&p;
    p.x = h[2]; p.y = h[3]; r.y = *(uint32_t*)&p;
    p.x = h[4]; p.y = h[5]; r.z = *(uint32_t*)&p;
    p.x = h[6]; p.y = h[7]; r.w = *(uint32_t*)&p;
    return r;
}

// ---------------- convB: W -> per-head [n][k] fp16 tiles ----------------------
// grid (64 kc, 8 head, 2 mode), 256 threads.
__global__ __launch_bounds__(256) void convB_kernel(
    const float* __restrict__ W_k, const float* __restrict__ W_v2)
{
    const int kc = blockIdx.x, h = blockIdx.y, mode = blockIdx.z, tid = threadIdx.x;
    const float* W = mode ? W_v2 : W_k;
    const int n = tid & 127;
    const int kh = (tid >> 7) * 8;
    float vals[8];
#pragma unroll
    for (int j = 0; j < 8; j++)
        vals[j] = W[(size_t)(kc * 16 + kh + j) * 1024 + h * 128 + n];
    const size_t base = ((size_t)(h * 64 + kc) * 128 + n) * 24 + kh;
    *(uint4*)&g_Bf[mode][base] = pack8_f16(vals);
}

// ---------------- small projections: q + v1 merged (grid.y = 2) --------------
__global__ __launch_bounds__(512) void small_proj_kernel(
    const float* __restrict__ Xq, const float* __restrict__ Wq,
    const float* __restrict__ bq, const float* __restrict__ gq, const float* __restrict__ betq,
    const float* __restrict__ Xv, const float* __restrict__ Wv,
    const float* __restrict__ bv, const float* __restrict__ gv, const float* __restrict__ betv)
{
    __shared__ float xs[1024];
    __shared__ float part[4][128];
    __shared__ float sh[16];
    const int row = blockIdx.x >> 3;
    const int h   = blockIdx.x & 7;
    const int dst = blockIdx.y;
    const int tid = threadIdx.x;
    const int c   = tid & 127;
    const int kq  = tid >> 7;

    const float* X     = dst ? Xv   : Xq;
    const float* W     = dst ? Wv   : Wq;
    const float* bias  = dst ? bv   : bq;
    const float* gw    = dst ? gv   : gq;
    const float* betaw = dst ? betv : betq;

    if (tid < 256)
        ((float4*)xs)[tid] = ((const float4*)(X + (size_t)row * 1024))[tid];
    __syncthreads();

    const int col = h * 128 + c;
    const float* Wp = W + (size_t)(kq * 256) * 1024 + col;
    const float* xp = xs + kq * 256;
    float a = 0.f;
#pragma unroll 16
    for (int k = 0; k < 256; k++) a = fmaf(xp[k], Wp[(size_t)k * 1024], a);
    part[kq][c] = a;
    __syncthreads();

    float acc = 0.f;
    if (tid < 128)
        acc = celu_f(part[0][c] + part[1][c] + part[2][c] + part[3][c] + bias[col]);

    float s = acc, s2 = acc * acc;
#pragma unroll
    for (int o = 16; o; o >>= 1) {
        s  += __shfl_xor_sync(0xffffffffu, s,  o);
        s2 += __shfl_xor_sync(0xffffffffu, s2, o);
    }
    if ((tid & 31) == 0) { sh[tid >> 5] = s; sh[(tid >> 5) + 8] = s2; }
    __syncthreads();
    if (tid < 128) {
        s  = sh[0] + sh[1] + sh[2]  + sh[3];
        s2 = sh[8] + sh[9] + sh[10] + sh[11];
        const float mu   = s * (1.f / 128.f);
        const float rstd = rsqrtf(s2 * (1.f / 128.f) - mu * mu + GNEPS);
        const float v = (acc - mu) * rstd * gw[col] + betaw[col];
        if (dst == 0) g_qbuf[row * 1024 + col] = v;
        else          g_v1buf[row * 1024 + col] = v;
    }
}

// ---------------- merged tensor-core big projection GEMM ---------------------
// grid (8 heads, 512 row-tiles, 2 modes), 256 thr = 8 warps (4M x 2N).
// mode 0 (key): single-pass fp16. mode 1 (value2): 2-pass fp16-split A x fp16 B.
__global__ __launch_bounds__(256, 2) void big_mma_kernel(
    const float* __restrict__ key,  const float* __restrict__ value2,
    const float* __restrict__ b_k,  const float* __restrict__ g_k,  const float* __restrict__ beta_k,
    const float* __restrict__ b_v,  const float* __restrict__ g_v,  const float* __restrict__ beta_v)
{
    __shared__ __align__(16) __half sAhi[128][24];
    __shared__ __align__(16) __half sAlo[128][24];
    __shared__ __align__(16) __half sB[2][128][24];
    __shared__ float sbias[128], sg[128], sbeta[128], sq[128];
    __shared__ float psum[128][2], psum2[128][2];
    __shared__ float pdot[128][2], pk2[128][2];

    const int h    = blockIdx.x;
    const int tm   = blockIdx.y;
    const int mode = blockIdx.z;
    const int tid  = threadIdx.x;
    const int lane = tid & 31;
    const int warp = tid >> 5;
    const int wm   = warp >> 1;
    const int wn   = warp & 1;
    const int col0 = h * 128;
    const int b0   = tm >> 3;

    const float* A     = mode ? value2 : key;
    const float* bias  = mode ? b_v    : b_k;
    const float* gw    = mode ? g_v    : g_k;
    const float* betaw = mode ? beta_v : beta_k;

    if (tid < 128) {
        sbias[tid] = bias[col0 + tid];
        sg[tid]    = gw[col0 + tid];
        sbeta[tid] = betaw[col0 + tid];
        sq[tid]    = (mode == 0) ? g_qbuf[b0 * 1024 + col0 + tid] : 0.f;
    }

    const int ar = tid >> 1;
    const int ak = (tid & 1) * 8;
    const float* Abase = A + (size_t)(tm * 128 + ar) * 1024 + ak;

    float pf[8];
    auto ldgA = [&](int kc) {
        const float4* p = (const float4*)(Abase + kc * 16);
        *(float4*)&pf[0] = p[0];
        *(float4*)&pf[4] = p[1];
    };
    const uint32_t aHiRow = smem_u32(&sAhi[ar][ak]);
    const uint32_t aLoRow = smem_u32(&sAlo[ar][ak]);

    const __half* Bsrc = g_Bf[mode];
    const uint32_t sB0 = smem_u32(&sB[0][0][0]);
    auto cpB = [&](int kc, int stg) {
        const size_t tb = (size_t)(h * 64 + kc) * 3072;
        const uint32_t d = sB0 + (uint32_t)stg * 6144u;
        cp16(d + (uint32_t)tid * 16u, Bsrc + tb + (size_t)tid * 8);
        if (tid < 128) cp16(d + (uint32_t)(tid + 256) * 16u, Bsrc + tb + (size_t)(tid + 256) * 8);
    };

    const uint32_t aHi = smem_u32(sAhi), aLo = smem_u32(sAlo);
    const uint32_t klane = (uint32_t)(((lane >> 4) & 1) * 16);
    uint32_t aoff[2];
#pragma unroll
    for (int mt = 0; mt < 2; mt++) {
        const int r = wm * 32 + mt * 16 + (lane & 7) + 8 * ((lane >> 3) & 1);
        aoff[mt] = (uint32_t)r * 48u + klane;
    }
    uint32_t boff[4];
#pragma unroll
    for (int bp = 0; bp < 4; bp++) {
        const int n = wn * 64 + bp * 16 + (lane & 7) + 8 * ((lane >> 3) & 1);
        boff[bp] = (uint32_t)n * 48u + klane;
    }

    float acc[2][8][4];
#pragma unroll
    for (int mt = 0; mt < 2; mt++)
#pragma unroll
        for (int nf = 0; nf < 8; nf++)
#pragma unroll
            for (int q = 0; q < 4; q++) acc[mt][nf][q] = 0.f;

    ldgA(0);
    cpB(0, 0);
    CP_COMMIT();

    for (int kc = 0; kc < 64; kc++) {
        // store A: hi (both modes) + lo (mode 1 only, fp16 residual split)
        if (mode == 0) {
            *(uint4*)__cvta_shared_to_generic(aHiRow) = pack8_f16(pf);
        } else {
            float rem[8];
            const uint4 hi = pack_hi8_f16(pf, rem);
            const uint4 lo = pack8_f16(rem);
            *(uint4*)__cvta_shared_to_generic(aHiRow) = hi;
            *(uint4*)__cvta_shared_to_generic(aLoRow) = lo;
        }
        if (kc < 63) { cpB(kc + 1, (kc + 1) & 1); CP_COMMIT(); CP_WAIT1(); }
        else         { CP_WAIT0(); }
        __syncthreads();
        if (kc < 63) ldgA(kc + 1);

        const uint32_t bbase = sB0 + (uint32_t)(kc & 1) * 6144u;
        uint32_t ah[2][4], al[2][4];
#pragma unroll
        for (int mt = 0; mt < 2; mt++) ldsm4(ah[mt], aHi + aoff[mt]);
        if (mode != 0) {
#pragma unroll
            for (int mt = 0; mt < 2; mt++) ldsm4(al[mt], aLo + aoff[mt]);
        }
#pragma unroll
        for (int bp = 0; bp < 4; bp++) {
            uint32_t bh[4];
            ldsm4(bh, bbase + boff[bp]);
#pragma unroll
            for (int mt = 0; mt < 2; mt++) {
                mma16816h(acc[mt][2 * bp],     ah[mt], bh[0], bh[2]);
                mma16816h(acc[mt][2 * bp + 1], ah[mt], bh[1], bh[3]);
            }
            if (mode != 0) {
#pragma unroll
                for (int mt = 0; mt < 2; mt++) {
                    mma16816h(acc[mt][2 * bp],     al[mt], bh[0], bh[2]);
                    mma16816h(acc[mt][2 * bp + 1], al[mt], bh[1], bh[3]);
                }
            }
        }
        __syncthreads();
    }

    // ---- register epilogue (proven) ----
    const int bh2 = b0 * 8 + h;
#pragma unroll
    for (int mt = 0; mt < 2; mt++)
#pragma unroll
        for (int nf = 0; nf < 8; nf++) {
            const int c = wn * 64 + nf * 8 + 2 * (lane & 3);
            acc[mt][nf][0] = celu_f(acc[mt][nf][0] + sbias[c]);
            acc[mt][nf][1] = celu_f(acc[mt][nf][1] + sbias[c + 1]);
            acc[mt][nf][2] = celu_f(acc[mt][nf][2] + sbias[c]);
            acc[mt][nf][3] = celu_f(acc[mt][nf][3] + sbias[c + 1]);
        }

#pragma unroll
    for (int mt = 0; mt < 2; mt++) {
        float sA = 0.f, s2A = 0.f, sBv = 0.f, s2B = 0.f;
#pragma unroll
        for (int nf = 0; nf < 8; nf++) {
            sA += acc[mt][nf][0] + acc[mt][nf][1];
            s2A = fmaf(acc[mt][nf][0], acc[mt][nf][0], fmaf(acc[mt][nf][1], acc[mt][nf][1], s2A));
            sBv += acc[mt][nf][2] + acc[mt][nf][3];
            s2B = fmaf(acc[mt][nf][2], acc[mt][nf][2], fmaf(acc[mt][nf][3], acc[mt][nf][3], s2B));
        }
        sA = quad2(sA); s2A = quad2(s2A); sBv = quad2(sBv); s2B = quad2(s2B);
        if ((lane & 3) == 0) {
            const int R = wm * 32 + mt * 16 + (lane >> 2);
            psum[R][wn] = sA;       psum2[R][wn] = s2A;
            psum[R + 8][wn] = sBv;  psum2[R + 8][wn] = s2B;
        }
    }
    __syncthreads();

    float mu_[2][2], rs_[2][2];
#pragma unroll
    for (int mt = 0; mt < 2; mt++)
#pragma unroll
        for (int hf = 0; hf < 2; hf++) {
            const int R = wm * 32 + mt * 16 + (lane >> 2) + 8 * hf;
            const float S  = psum[R][0] + psum[R][1];
            const float S2 = psum2[R][0] + psum2[R][1];
            const float mu = S * (1.f / 128.f);
            mu_[mt][hf] = mu;
            rs_[mt][hf] = rsqrtf(S2 * (1.f / 128.f) - mu * mu + GNEPS);
        }

    if (mode == 0) {
#pragma unroll
        for (int mt = 0; mt < 2; mt++) {
            float dpA = 0.f, k2A = 0.f, dpB = 0.f, k2B = 0.f;
#pragma unroll
            for (int nf = 0; nf < 8; nf++) {
                const int c = wn * 64 + nf * 8 + 2 * (lane & 3);
                float v0 = (acc[mt][nf][0] - mu_[mt][0]) * rs_[mt][0] * sg[c]     + sbeta[c];
                float v1 = (acc[mt][nf][1] - mu_[mt][0]) * rs_[mt][0] * sg[c + 1] + sbeta[c + 1];
                float v2 = (acc[mt][nf][2] - mu_[mt][1]) * rs_[mt][1] * sg[c]     + sbeta[c];
                float v3 = (acc[mt][nf][3] - mu_[mt][1]) * rs_[mt][1] * sg[c + 1] + sbeta[c + 1];
                dpA = fmaf(v0, sq[c], fmaf(v1, sq[c + 1], dpA));
                k2A = fmaf(v0, v0, fmaf(v1, v1, k2A));
                dpB = fmaf(v2, sq[c], fmaf(v3, sq[c + 1], dpB));
                k2B = fmaf(v2, v2, fmaf(v3, v3, k2B));
            }
            dpA = quad2(dpA); k2A = quad2(k2A); dpB = quad2(dpB); k2B = quad2(k2B);
            if ((lane & 3) == 0) {
                const int R = wm * 32 + mt * 16 + (lane >> 2);
                pdot[R][wn] = dpA;      pk2[R][wn] = k2A;
                pdot[R + 8][wn] = dpB;  pk2[R + 8][wn] = k2B;
            }
        }
        __syncthreads();
        if (wn == 0 && (lane & 3) == 0) {
#pragma unroll
            for (int mt = 0; mt < 2; mt++)
#pragma unroll
                for (int hf = 0; hf < 2; hf++) {
                    const int R = wm * 32 + mt * 16 + (lane >> 2) + 8 * hf;
                    const int m = (tm * 128 + R) & 1023;
                    g_dotb[bh2 * 1024 + m] = pdot[R][0] + pdot[R][1];
                    g_knb[bh2 * 1024 + m]  = sqrtf(pk2[R][0] + pk2[R][1]);
                }
        }
    } else {
#pragma unroll
        for (int mt = 0; mt < 2; mt++)
#pragma unroll
            for (int hf = 0; hf < 2; hf++) {
                const int R = wm * 32 + mt * 16 + (lane >> 2) + 8 * hf;
                const int m = (tm * 128 + R) & 1023;
                __half* dst = g_v2h + ((size_t)bh2 * 1024 + m) * 128;
                const float mu = mu_[mt][hf], rstd = rs_[mt][hf];
#pragma unroll
                for (int nf = 0; nf < 8; nf++) {
                    const int c = wn * 64 + nf * 8 + 2 * (lane & 3);
                    const float v0 = (acc[mt][nf][2 * hf]     - mu) * rstd * sg[c]     + sbeta[c];
                    const float v1 = (acc[mt][nf][2 * hf + 1] - mu) * rstd * sg[c + 1] + sbeta[c + 1];
                    *(__half2*)(dst + c) = __floats2half2_rn(v0, v1);
                }
            }
    }
}

// ---------------- attention / pooling / output (256 threads) -----------------
__device__ __forceinline__ float bsum256(float v, float* sh) {
#pragma unroll
    for (int o = 16; o; o >>= 1) v += __shfl_xor_sync(0xffffffffu, v, o);
    if ((threadIdx.x & 31) == 0) sh[threadIdx.x >> 5] = v;
    __syncthreads();
    v = (sh[0] + sh[1]) + (sh[2] + sh[3]) + ((sh[4] + sh[5]) + (sh[6] + sh[7]));
    __syncthreads();
    return v;
}
__device__ __forceinline__ float bmax256(float v, float* sh) {
#pragma unroll
    for (int o = 16; o; o >>= 1) v = fmaxf(v, __shfl_xor_sync(0xffffffffu, v, o));
    if ((threadIdx.x & 31) == 0) sh[threadIdx.x >> 5] = v;
    __syncthreads();
    v = fmaxf(fmaxf(fmaxf(sh[0], sh[1]), fmaxf(sh[2], sh[3])),
              fmaxf(fmaxf(sh[4], sh[5]), fmaxf(sh[6], sh[7])));
    __syncthreads();
    return v;
}

__global__ __launch_bounds__(256) void attn_kernel(
    const float* __restrict__ mask,
    const float* __restrict__ W1,  const float* __restrict__ b1,
    const float* __restrict__ Wl,  const float* __restrict__ bl,
    const float* __restrict__ Wl2, const float* __restrict__ bl2,
    float* __restrict__ out)
{
    __shared__ float qdir[128], u[64], b1s[64], wls[64], pool[64];
    __shared__ float cosv[1024], aspv[1024], maskv[1024];
    __shared__ float pp[4][64];
    __shared__ float vo[4][128];
    __shared__ float sh[8];

    const int bh  = blockIdx.x;
    const int b   = bh >> 3;
    const int tid = threadIdx.x;

    const float qv = (tid < 128) ? g_qbuf[bh * 128 + tid] : 0.f;
    const float qn = sqrtf(bsum256(qv * qv, sh));
    if (tid < 128) qdir[tid] = qv / fmaxf(qn, 1e-12f);
    if (tid < 64) { b1s[tid] = b1[tid]; wls[tid] = Wl[tid]; }
    __syncthreads();

    if (tid < 64) {
        float a = 0.f;
#pragma unroll 4
        for (int d = 0; d < 128; d++) a = fmaf(qdir[d], W1[d * 64 + tid], a);
        u[tid] = a;
    }
    __syncthreads();

    const float qnc = fmaxf(qn, 1e-8f);
    const float bl0 = bl[0];

    float lmax = -1e30f, msum = 0.f;
#pragma unroll
    for (int mi = 0; mi < 4; mi++) {
        const int m = tid + mi * 256;
        const float kn = g_knb[bh * 1024 + m];
        const float cs = g_dotb[bh * 1024 + m] / (qnc * fmaxf(kn, 1e-8f));
        cosv[m] = cs;
        const float mk = mask[b * 1024 + m];
        maskv[m] = mk;
        msum += mk;
        float lg = bl0;
#pragma unroll 8
        for (int j = 0; j < 64; j++)
            lg = fmaf(fmaxf(fmaf(cs, u[j], b1s[j]), 0.f), wls[j], lg);
        if (mk == 0.f) lg = -1e9f;
        aspv[m] = lg;
        lmax = fmaxf(lmax, lg);
    }
    lmax = bmax256(lmax, sh);
    msum = bsum256(msum, sh);

    float esum = 0.f;
#pragma unroll
    for (int mi = 0; mi < 4; mi++) {
        const int m = tid + mi * 256;
        const float e = expf(aspv[m] - lmax);
        aspv[m] = e;
        esum += e;
    }
    esum = bsum256(esum, sh);
    const float inv = 1.f / esum;
    __syncthreads();

    {
        const int j = tid & 63, qtr = tid >> 6;
        const float uj = u[j], bj = b1s[j];
        float p = 0.f;
        const int m0 = qtr * 256;
#pragma unroll 8
        for (int m = m0; m < m0 + 256; m++)
            p = fmaf(fmaxf(fmaf(cosv[m], uj, bj), 0.f), maskv[m], p);
        pp[qtr][j] = p;
    }
    __syncthreads();
    if (tid < 64)
        pool[tid] = (pp[0][tid] + pp[1][tid] + pp[2][tid] + pp[3][tid]) / msum;
    __syncthreads();

    {
        const int cc = (tid & 63) * 2, qtr = tid >> 6;
        const __half2* vb = (const __half2*)(g_v2h + (size_t)bh * 131072
                                             + (size_t)(qtr * 256) * 128 + cc);
        const float* av = aspv + qtr * 256;
        float ax = 0.f, ay = 0.f;
#pragma unroll 8
        for (int m = 0; m < 256; m++) {
            const float2 hv = __half22float2(vb[(size_t)m * 64]);
            const float w = av[m];
            ax = fmaf(w, hv.x, ax);
            ay = fmaf(w, hv.y, ay);
        }
        vo[qtr][cc] = ax;
        vo[qtr][cc + 1] = ay;
    }
    __syncthreads();

    if (tid < 128) {
        float a2 = bl2[tid];
#pragma unroll 8
        for (int j = 0; j < 64; j++) a2 = fmaf(pool[j], Wl2[j * 128 + tid], a2);
        const float ach = 1.f / (1.f + expf(-a2));
        const float v2o = (vo[0][tid] + vo[1][tid] + vo[2][tid] + vo[3][tid]) * inv;
        out[bh * 128 + tid] = g_v1buf[bh * 128 + tid] * v2o * ach;
    }
}

// ---------------- launch ------------------------------------------------------
extern "C" void kernel_launch(void* const* d_in, const int* in_sizes, int n_in,
                              void* d_out, int out_size) {
    const float* query   = (const float*)d_in[0];
    const float* key     = (const float*)d_in[1];
    const float* mask    = (const float*)d_in[2];
    const float* value1  = (const float*)d_in[3];
    const float* value2  = (const float*)d_in[4];
    const float* W_q     = (const float*)d_in[5];
    const float* b_q     = (const float*)d_in[6];
    const float* g_q     = (const float*)d_in[7];
    const float* beta_q  = (const float*)d_in[8];
    const float* W_k     = (const float*)d_in[9];
    const float* b_k     = (const float*)d_in[10];
    const float* g_k     = (const float*)d_in[11];
    const float* beta_k  = (const float*)d_in[12];
    const float* W_v1    = (const float*)d_in[13];
    const float* b_v1    = (const float*)d_in[14];
    const float* g_v1    = (const float*)d_in[15];
    const float* beta_v1 = (const float*)d_in[16];
    const float* W_v2    = (const float*)d_in[17];
    const float* b_v2    = (const float*)d_in[18];
    const float* g_v2    = (const float*)d_in[19];
    const float* beta_v2 = (const float*)d_in[20];
    const float* W1      = (const float*)d_in[21];
    const float* b1      = (const float*)d_in[22];
    const float* Wl      = (const float*)d_in[23];
    const float* bl      = (const float*)d_in[24];
    const float* Wl2     = (const float*)d_in[25];
    const float* bl2     = (const float*)d_in[26];
    float* out = (float*)d_out;

    convB_kernel<<<dim3(64, 8, 2), 256>>>(W_k, W_v2);

    small_proj_kernel<<<dim3(512, 2), 512>>>(query,  W_q,  b_q,  g_q,  beta_q,
                                             value1, W_v1, b_v1, g_v1, beta_v1);

    big_mma_kernel<<<dim3(8, 512, 2), 256>>>(key, value2,
                                             b_k,  g_k,  beta_k,
                                             b_v2, g_v2, beta_v2);

    attn_kernel<<<512, 256>>>(mask, W1, b1, Wl, bl, Wl2, bl2, out);
}

// round 14
// speedup vs baseline: 1.3706x; 1.2051x over previous
#include <cuda_runtime.h>
#include <cuda_bf16.h>
#include <cuda_fp16.h>
#include <math.h>
#include <stdint.h>

#define ALPHA 1.3f
#define GNEPS 1e-5f
// B=64, M=1024, D=1024, H=8, HD=128

// ---------------- scratch (__device__ globals) -------------------------------
__device__ float g_qbuf[64 * 1024];
__device__ float g_v1buf[64 * 1024];
__device__ float g_dotb[64 * 8 * 1024];
__device__ float g_knb[64 * 8 * 1024];
__device__ __half g_v2h[67108864];             // v2 projected fp16

// Pre-converted W^T tiles (fp16): [mode][ (h*64+kc)*128 + n ]*24 + k
__device__ __half g_Bf[2][1572864];

__device__ __forceinline__ float celu_f(float x) {
    return x > 0.f ? x : ALPHA * expm1f(x * (1.0f / ALPHA));
}

// ---------------- PTX helpers ------------------------------------------------
__device__ __forceinline__ uint32_t smem_u32(const void* p) {
    return (uint32_t)__cvta_generic_to_shared(p);
}
__device__ __forceinline__ void cp16(uint32_t dst, const void* src) {
    asm volatile("cp.async.cg.shared.global [%0], [%1], 16;\n"
                 :: "r"(dst), "l"(__cvta_generic_to_global(src)));
}
#define CP_COMMIT()  asm volatile("cp.async.commit_group;\n" ::: "memory")
#define CP_WAIT1()   asm volatile("cp.async.wait_group 1;\n" ::: "memory")
#define CP_WAIT0()   asm volatile("cp.async.wait_group 0;\n" ::: "memory")

__device__ __forceinline__ void ldsm4(uint32_t* d, uint32_t addr) {
    asm volatile("ldmatrix.sync.aligned.m8n8.x4.shared.b16 {%0,%1,%2,%3}, [%4];"
                 : "=r"(d[0]), "=r"(d[1]), "=r"(d[2]), "=r"(d[3]) : "r"(addr));
}
__device__ __forceinline__ void mma16816h(float* c, const uint32_t* a,
                                          uint32_t b0, uint32_t b1) {
    asm volatile(
        "mma.sync.aligned.m16n8k16.row.col.f32.f16.f16.f32 "
        "{%0,%1,%2,%3}, {%4,%5,%6,%7}, {%8,%9}, {%0,%1,%2,%3};"
        : "+f"(c[0]), "+f"(c[1]), "+f"(c[2]), "+f"(c[3])
        : "r"(a[0]), "r"(a[1]), "r"(a[2]), "r"(a[3]), "r"(b0), "r"(b1));
}
__device__ __forceinline__ float quad2(float v) {
    v += __shfl_xor_sync(0xffffffffu, v, 1);
    v += __shfl_xor_sync(0xffffffffu, v, 2);
    return v;
}
__device__ __forceinline__ uint4 pack8_f16(const float* v) {
    uint4 r;
    __half2 p;
    p = __floats2half2_rn(v[0], v[1]); r.x = *(uint32_t*)&p;
    p = __floats2half2_rn(v[2], v[3]); r.y = *(uint32_t*)&p;
    p = __floats2half2_rn(v[4], v[5]); r.z = *(uint32_t*)&p;
    p = __floats2half2_rn(v[6], v[7]); r.w = *(uint32_t*)&p;
    return r;
}

// ---------------- convB: W -> per-head [n][k] fp16 tiles ----------------------
__global__ __launch_bounds__(256) void convB_kernel(
    const float* __restrict__ W_k, const float* __restrict__ W_v2)
{
    const int kc = blockIdx.x, h = blockIdx.y, mode = blockIdx.z, tid = threadIdx.x;
    const float* W = mode ? W_v2 : W_k;
    const int n = tid & 127;
    const int kh = (tid >> 7) * 8;
    float vals[8];
#pragma unroll
    for (int j = 0; j < 8; j++)
        vals[j] = W[(size_t)(kc * 16 + kh + j) * 1024 + h * 128 + n];
    const size_t base = ((size_t)(h * 64 + kc) * 128 + n) * 24 + kh;
    *(uint4*)&g_Bf[mode][base] = pack8_f16(vals);
}

// ---------------- small projections: q + v1 merged (grid.y = 2) --------------
__global__ __launch_bounds__(512) void small_proj_kernel(
    const float* __restrict__ Xq, const float* __restrict__ Wq,
    const float* __restrict__ bq, const float* __restrict__ gq, const float* __restrict__ betq,
    const float* __restrict__ Xv, const float* __restrict__ Wv,
    const float* __restrict__ bv, const float* __restrict__ gv, const float* __restrict__ betv)
{
    __shared__ float xs[1024];
    __shared__ float part[4][128];
    __shared__ float sh[16];
    const int row = blockIdx.x >> 3;
    const int h   = blockIdx.x & 7;
    const int dst = blockIdx.y;
    const int tid = threadIdx.x;
    const int c   = tid & 127;
    const int kq  = tid >> 7;

    const float* X     = dst ? Xv   : Xq;
    const float* W     = dst ? Wv   : Wq;
    const float* bias  = dst ? bv   : bq;
    const float* gw    = dst ? gv   : gq;
    const float* betaw = dst ? betv : betq;

    if (tid < 256)
        ((float4*)xs)[tid] = ((const float4*)(X + (size_t)row * 1024))[tid];
    __syncthreads();

    const int col = h * 128 + c;
    const float* Wp = W + (size_t)(kq * 256) * 1024 + col;
    const float* xp = xs + kq * 256;
    float a = 0.f;
#pragma unroll 16
    for (int k = 0; k < 256; k++) a = fmaf(xp[k], Wp[(size_t)k * 1024], a);
    part[kq][c] = a;
    __syncthreads();

    float acc = 0.f;
    if (tid < 128)
        acc = celu_f(part[0][c] + part[1][c] + part[2][c] + part[3][c] + bias[col]);

    float s = acc, s2 = acc * acc;
#pragma unroll
    for (int o = 16; o; o >>= 1) {
        s  += __shfl_xor_sync(0xffffffffu, s,  o);
        s2 += __shfl_xor_sync(0xffffffffu, s2, o);
    }
    if ((tid & 31) == 0) { sh[tid >> 5] = s; sh[(tid >> 5) + 8] = s2; }
    __syncthreads();
    if (tid < 128) {
        s  = sh[0] + sh[1] + sh[2]  + sh[3];
        s2 = sh[8] + sh[9] + sh[10] + sh[11];
        const float mu   = s * (1.f / 128.f);
        const float rstd = rsqrtf(s2 * (1.f / 128.f) - mu * mu + GNEPS);
        const float v = (acc - mu) * rstd * gw[col] + betaw[col];
        if (dst == 0) g_qbuf[row * 1024 + col] = v;
        else          g_v1buf[row * 1024 + col] = v;
    }
}

// ---------------- merged tensor-core big projection GEMM ---------------------
// grid (8 heads, 512 row-tiles, 2 modes), 256 thr = 8 warps (4M x 2N).
// UNIFORM single-pass fp16 mainloop; mode branch only in epilogue.
__global__ __launch_bounds__(256, 2) void big_mma_kernel(
    const float* __restrict__ key,  const float* __restrict__ value2,
    const float* __restrict__ b_k,  const float* __restrict__ g_k,  const float* __restrict__ beta_k,
    const float* __restrict__ b_v,  const float* __restrict__ g_v,  const float* __restrict__ beta_v)
{
    __shared__ __align__(16) __half sA[128][24];
    __shared__ __align__(16) __half sB[2][128][24];
    __shared__ float sbias[128], sg[128], sbeta[128], sq[128];
    __shared__ float psum[128][2], psum2[128][2];
    __shared__ float pdot[128][2], pk2[128][2];

    const int h    = blockIdx.x;
    const int tm   = blockIdx.y;
    const int mode = blockIdx.z;
    const int tid  = threadIdx.x;
    const int lane = tid & 31;
    const int warp = tid >> 5;
    const int wm   = warp >> 1;
    const int wn   = warp & 1;
    const int col0 = h * 128;
    const int b0   = tm >> 3;

    const float* A     = mode ? value2 : key;
    const float* bias  = mode ? b_v    : b_k;
    const float* gw    = mode ? g_v    : g_k;
    const float* betaw = mode ? beta_v : beta_k;

    if (tid < 128) {
        sbias[tid] = bias[col0 + tid];
        sg[tid]    = gw[col0 + tid];
        sbeta[tid] = betaw[col0 + tid];
        sq[tid]    = (mode == 0) ? g_qbuf[b0 * 1024 + col0 + tid] : 0.f;
    }

    const int ar = tid >> 1;
    const int ak = (tid & 1) * 8;
    const float* Abase = A + (size_t)(tm * 128 + ar) * 1024 + ak;

    float pf[8];
    auto ldgA = [&](int kc) {
        const float4* p = (const float4*)(Abase + kc * 16);
        *(float4*)&pf[0] = p[0];
        *(float4*)&pf[4] = p[1];
    };
    const uint32_t aRow = smem_u32(&sA[ar][ak]);

    const __half* Bsrc = g_Bf[mode];
    const uint32_t sB0 = smem_u32(&sB[0][0][0]);
    auto cpB = [&](int kc, int stg) {
        const size_t tb = (size_t)(h * 64 + kc) * 3072;
        const uint32_t d = sB0 + (uint32_t)stg * 6144u;
        cp16(d + (uint32_t)tid * 16u, Bsrc + tb + (size_t)tid * 8);
        if (tid < 128) cp16(d + (uint32_t)(tid + 256) * 16u, Bsrc + tb + (size_t)(tid + 256) * 8);
    };

    const uint32_t aSm = smem_u32(sA);
    const uint32_t klane = (uint32_t)(((lane >> 4) & 1) * 16);
    uint32_t aoff[2];
#pragma unroll
    for (int mt = 0; mt < 2; mt++) {
        const int r = wm * 32 + mt * 16 + (lane & 7) + 8 * ((lane >> 3) & 1);
        aoff[mt] = (uint32_t)r * 48u + klane;
    }
    uint32_t boff[4];
#pragma unroll
    for (int bp = 0; bp < 4; bp++) {
        const int n = wn * 64 + bp * 16 + (lane & 7) + 8 * ((lane >> 3) & 1);
        boff[bp] = (uint32_t)n * 48u + klane;
    }

    float acc[2][8][4];
#pragma unroll
    for (int mt = 0; mt < 2; mt++)
#pragma unroll
        for (int nf = 0; nf < 8; nf++)
#pragma unroll
            for (int q = 0; q < 4; q++) acc[mt][nf][q] = 0.f;

    ldgA(0);
    cpB(0, 0);
    CP_COMMIT();

    for (int kc = 0; kc < 64; kc++) {
        *(uint4*)__cvta_shared_to_generic(aRow) = pack8_f16(pf);
        if (kc < 63) { cpB(kc + 1, (kc + 1) & 1); CP_COMMIT(); CP_WAIT1(); }
        else         { CP_WAIT0(); }
        __syncthreads();
        if (kc < 63) ldgA(kc + 1);

        const uint32_t bbase = sB0 + (uint32_t)(kc & 1) * 6144u;
        uint32_t ah[2][4];
#pragma unroll
        for (int mt = 0; mt < 2; mt++) ldsm4(ah[mt], aSm + aoff[mt]);
#pragma unroll
        for (int bp = 0; bp < 4; bp++) {
            uint32_t bh[4];
            ldsm4(bh, bbase + boff[bp]);
#pragma unroll
            for (int mt = 0; mt < 2; mt++) {
                mma16816h(acc[mt][2 * bp],     ah[mt], bh[0], bh[2]);
                mma16816h(acc[mt][2 * bp + 1], ah[mt], bh[1], bh[3]);
            }
        }
        __syncthreads();
    }

    // ---- register epilogue (proven) ----
    const int bh2 = b0 * 8 + h;
#pragma unroll
    for (int mt = 0; mt < 2; mt++)
#pragma unroll
        for (int nf = 0; nf < 8; nf++) {
            const int c = wn * 64 + nf * 8 + 2 * (lane & 3);
            acc[mt][nf][0] = celu_f(acc[mt][nf][0] + sbias[c]);
            acc[mt][nf][1] = celu_f(acc[mt][nf][1] + sbias[c + 1]);
            acc[mt][nf][2] = celu_f(acc[mt][nf][2] + sbias[c]);
            acc[mt][nf][3] = celu_f(acc[mt][nf][3] + sbias[c + 1]);
        }

#pragma unroll
    for (int mt = 0; mt < 2; mt++) {
        float sA2 = 0.f, s2A = 0.f, sBv = 0.f, s2B = 0.f;
#pragma unroll
        for (int nf = 0; nf < 8; nf++) {
            sA2 += acc[mt][nf][0] + acc[mt][nf][1];
            s2A = fmaf(acc[mt][nf][0], acc[mt][nf][0], fmaf(acc[mt][nf][1], acc[mt][nf][1], s2A));
            sBv += acc[mt][nf][2] + acc[mt][nf][3];
            s2B = fmaf(acc[mt][nf][2], acc[mt][nf][2], fmaf(acc[mt][nf][3], acc[mt][nf][3], s2B));
        }
        sA2 = quad2(sA2); s2A = quad2(s2A); sBv = quad2(sBv); s2B = quad2(s2B);
        if ((lane & 3) == 0) {
            const int R = wm * 32 + mt * 16 + (lane >> 2);
            psum[R][wn] = sA2;      psum2[R][wn] = s2A;
            psum[R + 8][wn] = sBv;  psum2[R + 8][wn] = s2B;
        }
    }
    __syncthreads();

    float mu_[2][2], rs_[2][2];
#pragma unroll
    for (int mt = 0; mt < 2; mt++)
#pragma unroll
        for (int hf = 0; hf < 2; hf++) {
            const int R = wm * 32 + mt * 16 + (lane >> 2) + 8 * hf;
            const float S  = psum[R][0] + psum[R][1];
            const float S2 = psum2[R][0] + psum2[R][1];
            const float mu = S * (1.f / 128.f);
            mu_[mt][hf] = mu;
            rs_[mt][hf] = rsqrtf(S2 * (1.f / 128.f) - mu * mu + GNEPS);
        }

    if (mode == 0) {
#pragma unroll
        for (int mt = 0; mt < 2; mt++) {
            float dpA = 0.f, k2A = 0.f, dpB = 0.f, k2B = 0.f;
#pragma unroll
            for (int nf = 0; nf < 8; nf++) {
                const int c = wn * 64 + nf * 8 + 2 * (lane & 3);
                float v0 = (acc[mt][nf][0] - mu_[mt][0]) * rs_[mt][0] * sg[c]     + sbeta[c];
                float v1 = (acc[mt][nf][1] - mu_[mt][0]) * rs_[mt][0] * sg[c + 1] + sbeta[c + 1];
                float v2 = (acc[mt][nf][2] - mu_[mt][1]) * rs_[mt][1] * sg[c]     + sbeta[c];
                float v3 = (acc[mt][nf][3] - mu_[mt][1]) * rs_[mt][1] * sg[c + 1] + sbeta[c + 1];
                dpA = fmaf(v0, sq[c], fmaf(v1, sq[c + 1], dpA));
                k2A = fmaf(v0, v0, fmaf(v1, v1, k2A));
                dpB = fmaf(v2, sq[c], fmaf(v3, sq[c + 1], dpB));
                k2B = fmaf(v2, v2, fmaf(v3, v3, k2B));
            }
            dpA = quad2(dpA); k2A = quad2(k2A); dpB = quad2(dpB); k2B = quad2(k2B);
            if ((lane & 3) == 0) {
                const int R = wm * 32 + mt * 16 + (lane >> 2);
                pdot[R][wn] = dpA;      pk2[R][wn] = k2A;
                pdot[R + 8][wn] = dpB;  pk2[R + 8][wn] = k2B;
            }
        }
        __syncthreads();
        if (wn == 0 && (lane & 3) == 0) {
#pragma unroll
            for (int mt = 0; mt < 2; mt++)
#pragma unroll
                for (int hf = 0; hf < 2; hf++) {
                    const int R = wm * 32 + mt * 16 + (lane >> 2) + 8 * hf;
                    const int m = (tm * 128 + R) & 1023;
                    g_dotb[bh2 * 1024 + m] = pdot[R][0] + pdot[R][1];
                    g_knb[bh2 * 1024 + m]  = sqrtf(pk2[R][0] + pk2[R][1]);
                }
        }
    } else {
#pragma unroll
        for (int mt = 0; mt < 2; mt++)
#pragma unroll
            for (int hf = 0; hf < 2; hf++) {
                const int R = wm * 32 + mt * 16 + (lane >> 2) + 8 * hf;
                const int m = (tm * 128 + R) & 1023;
                __half* dst = g_v2h + ((size_t)bh2 * 1024 + m) * 128;
                const float mu = mu_[mt][hf], rstd = rs_[mt][hf];
#pragma unroll
                for (int nf = 0; nf < 8; nf++) {
                    const int c = wn * 64 + nf * 8 + 2 * (lane & 3);
                    const float v0 = (acc[mt][nf][2 * hf]     - mu) * rstd * sg[c]     + sbeta[c];
                    const float v1 = (acc[mt][nf][2 * hf + 1] - mu) * rstd * sg[c + 1] + sbeta[c + 1];
                    *(__half2*)(dst + c) = __floats2half2_rn(v0, v1);
                }
            }
    }
}

// ---------------- attention / pooling / output (256 threads) -----------------
__device__ __forceinline__ float bsum256(float v, float* sh) {
#pragma unroll
    for (int o = 16; o; o >>= 1) v += __shfl_xor_sync(0xffffffffu, v, o);
    if ((threadIdx.x & 31) == 0) sh[threadIdx.x >> 5] = v;
    __syncthreads();
    v = (sh[0] + sh[1]) + (sh[2] + sh[3]) + ((sh[4] + sh[5]) + (sh[6] + sh[7]));
    __syncthreads();
    return v;
}
__device__ __forceinline__ float bmax256(float v, float* sh) {
#pragma unroll
    for (int o = 16; o; o >>= 1) v = fmaxf(v, __shfl_xor_sync(0xffffffffu, v, o));
    if ((threadIdx.x & 31) == 0) sh[threadIdx.x >> 5] = v;
    __syncthreads();
    v = fmaxf(fmaxf(fmaxf(sh[0], sh[1]), fmaxf(sh[2], sh[3])),
              fmaxf(fmaxf(sh[4], sh[5]), fmaxf(sh[6], sh[7])));
    __syncthreads();
    return v;
}

__global__ __launch_bounds__(256) void attn_kernel(
    const float* __restrict__ mask,
    const float* __restrict__ W1,  const float* __restrict__ b1,
    const float* __restrict__ Wl,  const float* __restrict__ bl,
    const float* __restrict__ Wl2, const float* __restrict__ bl2,
    float* __restrict__ out)
{
    __shared__ float qdir[128], u[64], b1s[64], wls[64], pool[64];
    __shared__ float cosv[1024], aspv[1024], maskv[1024];
    __shared__ float pp[4][64];
    __shared__ float vo[4][128];
    __shared__ float sh[8];

    const int bh  = blockIdx.x;
    const int b   = bh >> 3;
    const int tid = threadIdx.x;

    const float qv = (tid < 128) ? g_qbuf[bh * 128 + tid] : 0.f;
    const float qn = sqrtf(bsum256(qv * qv, sh));
    if (tid < 128) qdir[tid] = qv / fmaxf(qn, 1e-12f);
    if (tid < 64) { b1s[tid] = b1[tid]; wls[tid] = Wl[tid]; }
    __syncthreads();

    if (tid < 64) {
        float a = 0.f;
#pragma unroll 4
        for (int d = 0; d < 128; d++) a = fmaf(qdir[d], W1[d * 64 + tid], a);
        u[tid] = a;
    }
    __syncthreads();

    const float qnc = fmaxf(qn, 1e-8f);
    const float bl0 = bl[0];

    float lmax = -1e30f, msum = 0.f;
#pragma unroll
    for (int mi = 0; mi < 4; mi++) {
        const int m = tid + mi * 256;
        const float kn = g_knb[bh * 1024 + m];
        const float cs = g_dotb[bh * 1024 + m] / (qnc * fmaxf(kn, 1e-8f));
        cosv[m] = cs;
        const float mk = mask[b * 1024 + m];
        maskv[m] = mk;
        msum += mk;
        float lg = bl0;
#pragma unroll 8
        for (int j = 0; j < 64; j++)
            lg = fmaf(fmaxf(fmaf(cs, u[j], b1s[j]), 0.f), wls[j], lg);
        if (mk == 0.f) lg = -1e9f;
        aspv[m] = lg;
        lmax = fmaxf(lmax, lg);
    }
    lmax = bmax256(lmax, sh);
    msum = bsum256(msum, sh);

    float esum = 0.f;
#pragma unroll
    for (int mi = 0; mi < 4; mi++) {
        const int m = tid + mi * 256;
        const float e = expf(aspv[m] - lmax);
        aspv[m] = e;
        esum += e;
    }
    esum = bsum256(esum, sh);
    const float inv = 1.f / esum;
    __syncthreads();

    {
        const int j = tid & 63, qtr = tid >> 6;
        const float uj = u[j], bj = b1s[j];
        float p = 0.f;
        const int m0 = qtr * 256;
#pragma unroll 8
        for (int m = m0; m < m0 + 256; m++)
            p = fmaf(fmaxf(fmaf(cosv[m], uj, bj), 0.f), maskv[m], p);
        pp[qtr][j] = p;
    }
    __syncthreads();
    if (tid < 64)
        pool[tid] = (pp[0][tid] + pp[1][tid] + pp[2][tid] + pp[3][tid]) / msum;
    __syncthreads();

    {
        const int cc = (tid & 63) * 2, qtr = tid >> 6;
        const __half2* vb = (const __half2*)(g_v2h + (size_t)bh * 131072
                                             + (size_t)(qtr * 256) * 128 + cc);
        const float* av = aspv + qtr * 256;
        float ax = 0.f, ay = 0.f;
#pragma unroll 8
        for (int m = 0; m < 256; m++) {
            const float2 hv = __half22float2(vb[(size_t)m * 64]);
            const float w = av[m];
            ax = fmaf(w, hv.x, ax);
            ay = fmaf(w, hv.y, ay);
        }
        vo[qtr][cc] = ax;
        vo[qtr][cc + 1] = ay;
    }
    __syncthreads();

    if (tid < 128) {
        float a2 = bl2[tid];
#pragma unroll 8
        for (int j = 0; j < 64; j++) a2 = fmaf(pool[j], Wl2[j * 128 + tid], a2);
        const float ach = 1.f / (1.f + expf(-a2));
        const float v2o = (vo[0][tid] + vo[1][tid] + vo[2][tid] + vo[3][tid]) * inv;
        out[bh * 128 + tid] = g_v1buf[bh * 128 + tid] * v2o * ach;
    }
}

// ---------------- launch ------------------------------------------------------
extern "C" void kernel_launch(void* const* d_in, const int* in_sizes, int n_in,
                              void* d_out, int out_size) {
    const float* query   = (const float*)d_in[0];
    const float* key     = (const float*)d_in[1];
    const float* mask    = (const float*)d_in[2];
    const float* value1  = (const float*)d_in[3];
    const float* value2  = (const float*)d_in[4];
    const float* W_q     = (const float*)d_in[5];
    const float* b_q     = (const float*)d_in[6];
    const float* g_q     = (const float*)d_in[7];
    const float* beta_q  = (const float*)d_in[8];
    const float* W_k     = (const float*)d_in[9];
    const float* b_k     = (const float*)d_in[10];
    const float* g_k     = (const float*)d_in[11];
    const float* beta_k  = (const float*)d_in[12];
    const float* W_v1    = (const float*)d_in[13];
    const float* b_v1    = (const float*)d_in[14];
    const float* g_v1    = (const float*)d_in[15];
    const float* beta_v1 = (const float*)d_in[16];
    const float* W_v2    = (const float*)d_in[17];
    const float* b_v2    = (const float*)d_in[18];
    const float* g_v2    = (const float*)d_in[19];
    const float* beta_v2 = (const float*)d_in[20];
    const float* W1      = (const float*)d_in[21];
    const float* b1      = (const float*)d_in[22];
    const float* Wl      = (const float*)d_in[23];
    const float* bl      = (const float*)d_in[24];
    const float* Wl2     = (const float*)d_in[25];
    const float* bl2     = (const float*)d_in[26];
    float* out = (float*)d_out;

    convB_kernel<<<dim3(64, 8, 2), 256>>>(W_k, W_v2);

    small_proj_kernel<<<dim3(512, 2), 512>>>(query,  W_q,  b_q,  g_q,  beta_q,
                                             value1, W_v1, b_v1, g_v1, beta_v1);

    big_mma_kernel<<<dim3(8, 512, 2), 256>>>(key, value2,
                                             b_k,  g_k,  beta_k,
                                             b_v2, g_v2, beta_v2);

    attn_kernel<<<512, 256>>>(mask, W1, b1, Wl, bl, Wl2, bl2, out);
}

// round 15
// speedup vs baseline: 1.5297x; 1.1161x over previous
#include <cuda_runtime.h>
#include <cuda_bf16.h>
#include <cuda_fp16.h>
#include <math.h>
#include <stdint.h>

#define ALPHA 1.3f
#define GNEPS 1e-5f
// B=64, M=1024, D=1024, H=8, HD=128

// ---------------- scratch (__device__ globals) -------------------------------
__device__ float g_qbuf[64 * 1024];
__device__ float g_v1buf[64 * 1024];
__device__ float g_dotb[64 * 8 * 1024];
__device__ float g_knb[64 * 8 * 1024];
__device__ __half g_v2h[67108864];             // v2 projected fp16

// Pre-converted W^T tiles (fp16): [mode][ (h*32+kc)*128 + n ]*40 + k  (K=32 chunks, pad 40)
__device__ __half g_Bf[2][2621440];

__device__ __forceinline__ float celu_f(float x) {
    return x > 0.f ? x : ALPHA * expm1f(x * (1.0f / ALPHA));
}

// ---------------- PTX helpers ------------------------------------------------
__device__ __forceinline__ uint32_t smem_u32(const void* p) {
    return (uint32_t)__cvta_generic_to_shared(p);
}
__device__ __forceinline__ void cp16(uint32_t dst, const void* src) {
    asm volatile("cp.async.cg.shared.global [%0], [%1], 16;\n"
                 :: "r"(dst), "l"(__cvta_generic_to_global(src)));
}
#define CP_COMMIT()  asm volatile("cp.async.commit_group;\n" ::: "memory")
#define CP_WAIT1()   asm volatile("cp.async.wait_group 1;\n" ::: "memory")
#define CP_WAIT0()   asm volatile("cp.async.wait_group 0;\n" ::: "memory")

__device__ __forceinline__ void ldsm4(uint32_t* d, uint32_t addr) {
    asm volatile("ldmatrix.sync.aligned.m8n8.x4.shared.b16 {%0,%1,%2,%3}, [%4];"
                 : "=r"(d[0]), "=r"(d[1]), "=r"(d[2]), "=r"(d[3]) : "r"(addr));
}
__device__ __forceinline__ void mma16816h(float* c, const uint32_t* a,
                                          uint32_t b0, uint32_t b1) {
    asm volatile(
        "mma.sync.aligned.m16n8k16.row.col.f32.f16.f16.f32 "
        "{%0,%1,%2,%3}, {%4,%5,%6,%7}, {%8,%9}, {%0,%1,%2,%3};"
        : "+f"(c[0]), "+f"(c[1]), "+f"(c[2]), "+f"(c[3])
        : "r"(a[0]), "r"(a[1]), "r"(a[2]), "r"(a[3]), "r"(b0), "r"(b1));
}
__device__ __forceinline__ float quad2(float v) {
    v += __shfl_xor_sync(0xffffffffu, v, 1);
    v += __shfl_xor_sync(0xffffffffu, v, 2);
    return v;
}
__device__ __forceinline__ uint4 pack8_f16(const float* v) {
    uint4 r;
    __half2 p;
    p = __floats2half2_rn(v[0], v[1]); r.x = *(uint32_t*)&p;
    p = __floats2half2_rn(v[2], v[3]); r.y = *(uint32_t*)&p;
    p = __floats2half2_rn(v[4], v[5]); r.z = *(uint32_t*)&p;
    p = __floats2half2_rn(v[6], v[7]); r.w = *(uint32_t*)&p;
    return r;
}

// ---------------- convB: W -> per-head [n][k32] fp16 padded tiles -------------
// grid (32 kc, 8 head, 2 mode), 256 threads; thread: n = tid&127, kh = (tid>>7)*16
__global__ __launch_bounds__(256) void convB_kernel(
    const float* __restrict__ W_k, const float* __restrict__ W_v2)
{
    const int kc = blockIdx.x, h = blockIdx.y, mode = blockIdx.z, tid = threadIdx.x;
    const float* W = mode ? W_v2 : W_k;
    const int n = tid & 127;
    const int kh = (tid >> 7) * 16;
    float vals[16];
#pragma unroll
    for (int j = 0; j < 16; j++)
        vals[j] = W[(size_t)(kc * 32 + kh + j) * 1024 + h * 128 + n];
    const size_t base = ((size_t)(h * 32 + kc) * 128 + n) * 40 + kh;
    *(uint4*)&g_Bf[mode][base]     = pack8_f16(vals);
    *(uint4*)&g_Bf[mode][base + 8] = pack8_f16(vals + 8);
}

// ---------------- small projections: q + v1 merged (grid.y = 2) --------------
__global__ __launch_bounds__(512) void small_proj_kernel(
    const float* __restrict__ Xq, const float* __restrict__ Wq,
    const float* __restrict__ bq, const float* __restrict__ gq, const float* __restrict__ betq,
    const float* __restrict__ Xv, const float* __restrict__ Wv,
    const float* __restrict__ bv, const float* __restrict__ gv, const float* __restrict__ betv)
{
    __shared__ float xs[1024];
    __shared__ float part[4][128];
    __shared__ float sh[16];
    const int row = blockIdx.x >> 3;
    const int h   = blockIdx.x & 7;
    const int dst = blockIdx.y;
    const int tid = threadIdx.x;
    const int c   = tid & 127;
    const int kq  = tid >> 7;

    const float* X     = dst ? Xv   : Xq;
    const float* W     = dst ? Wv   : Wq;
    const float* bias  = dst ? bv   : bq;
    const float* gw    = dst ? gv   : gq;
    const float* betaw = dst ? betv : betq;

    if (tid < 256)
        ((float4*)xs)[tid] = ((const float4*)(X + (size_t)row * 1024))[tid];
    __syncthreads();

    const int col = h * 128 + c;
    const float* Wp = W + (size_t)(kq * 256) * 1024 + col;
    const float* xp = xs + kq * 256;
    float a = 0.f;
#pragma unroll 16
    for (int k = 0; k < 256; k++) a = fmaf(xp[k], Wp[(size_t)k * 1024], a);
    part[kq][c] = a;
    __syncthreads();

    float acc = 0.f;
    if (tid < 128)
        acc = celu_f(part[0][c] + part[1][c] + part[2][c] + part[3][c] + bias[col]);

    float s = acc, s2 = acc * acc;
#pragma unroll
    for (int o = 16; o; o >>= 1) {
        s  += __shfl_xor_sync(0xffffffffu, s,  o);
        s2 += __shfl_xor_sync(0xffffffffu, s2, o);
    }
    if ((tid & 31) == 0) { sh[tid >> 5] = s; sh[(tid >> 5) + 8] = s2; }
    __syncthreads();
    if (tid < 128) {
        s  = sh[0] + sh[1] + sh[2]  + sh[3];
        s2 = sh[8] + sh[9] + sh[10] + sh[11];
        const float mu   = s * (1.f / 128.f);
        const float rstd = rsqrtf(s2 * (1.f / 128.f) - mu * mu + GNEPS);
        const float v = (acc - mu) * rstd * gw[col] + betaw[col];
        if (dst == 0) g_qbuf[row * 1024 + col] = v;
        else          g_v1buf[row * 1024 + col] = v;
    }
}

// ---------------- merged tensor-core big projection GEMM ---------------------
// grid (8 heads, 512 row-tiles, 2 modes), 256 thr = 8 warps (4M x 2N).
// Single-pass fp16, K-chunk 32 (32 iterations, half the barriers of K16).
__global__ __launch_bounds__(256, 2) void big_mma_kernel(
    const float* __restrict__ key,  const float* __restrict__ value2,
    const float* __restrict__ b_k,  const float* __restrict__ g_k,  const float* __restrict__ beta_k,
    const float* __restrict__ b_v,  const float* __restrict__ g_v,  const float* __restrict__ beta_v)
{
    __shared__ __align__(16) __half sA[128][40];       // 10KB
    __shared__ __align__(16) __half sB[2][128][40];    // 20KB
    __shared__ float sbias[128], sg[128], sbeta[128], sq[128];
    __shared__ float psum[128][2], psum2[128][2];
    __shared__ float pdot[128][2], pk2[128][2];

    const int h    = blockIdx.x;
    const int tm   = blockIdx.y;
    const int mode = blockIdx.z;
    const int tid  = threadIdx.x;
    const int lane = tid & 31;
    const int warp = tid >> 5;
    const int wm   = warp >> 1;
    const int wn   = warp & 1;
    const int col0 = h * 128;
    const int b0   = tm >> 3;

    const float* A     = mode ? value2 : key;
    const float* bias  = mode ? b_v    : b_k;
    const float* gw    = mode ? g_v    : g_k;
    const float* betaw = mode ? beta_v : beta_k;

    if (tid < 128) {
        sbias[tid] = bias[col0 + tid];
        sg[tid]    = gw[col0 + tid];
        sbeta[tid] = betaw[col0 + tid];
        sq[tid]    = (mode == 0) ? g_qbuf[b0 * 1024 + col0 + tid] : 0.f;
    }

    // A: thread -> (row, 16-float half of k32)
    const int ar = tid >> 1;
    const int ak = (tid & 1) * 16;
    const float* Abase = A + (size_t)(tm * 128 + ar) * 1024 + ak;

    float pf[16];
    auto ldgA = [&](int kc) {
        const float4* p = (const float4*)(Abase + kc * 32);
        *(float4*)&pf[0]  = p[0];
        *(float4*)&pf[4]  = p[1];
        *(float4*)&pf[8]  = p[2];
        *(float4*)&pf[12] = p[3];
    };
    const uint32_t aRow = smem_u32(&sA[ar][ak]);
    auto storeA = [&]() {
        *(uint4*)__cvta_shared_to_generic(aRow)       = pack8_f16(pf);
        *(uint4*)__cvta_shared_to_generic(aRow + 16u) = pack8_f16(pf + 8);
    };

    const __half* Bsrc = g_Bf[mode];
    const uint32_t sB0 = smem_u32(&sB[0][0][0]);
    auto cpB = [&](int kc, int stg) {
        const size_t tb = (size_t)(h * 32 + kc) * 5120;    // halves (128*40)
        const uint32_t d = sB0 + (uint32_t)stg * 10240u;
        cp16(d + (uint32_t)tid * 16u,           Bsrc + tb + (size_t)tid * 8);
        cp16(d + (uint32_t)(tid + 256) * 16u,   Bsrc + tb + (size_t)(tid + 256) * 8);
        if (tid < 128)
            cp16(d + (uint32_t)(tid + 512) * 16u, Bsrc + tb + (size_t)(tid + 512) * 8);
    };

    const uint32_t aSm = smem_u32(sA);
    const uint32_t klane = (uint32_t)(((lane >> 4) & 1) * 16);
    uint32_t aoff[2];
#pragma unroll
    for (int mt = 0; mt < 2; mt++) {
        const int r = wm * 32 + mt * 16 + (lane & 7) + 8 * ((lane >> 3) & 1);
        aoff[mt] = (uint32_t)r * 80u + klane;
    }
    uint32_t boff[4];
#pragma unroll
    for (int bp = 0; bp < 4; bp++) {
        const int n = wn * 64 + bp * 16 + (lane & 7) + 8 * ((lane >> 3) & 1);
        boff[bp] = (uint32_t)n * 80u + klane;
    }

    float acc[2][8][4];
#pragma unroll
    for (int mt = 0; mt < 2; mt++)
#pragma unroll
        for (int nf = 0; nf < 8; nf++)
#pragma unroll
            for (int q = 0; q < 4; q++) acc[mt][nf][q] = 0.f;

    ldgA(0);
    cpB(0, 0);
    CP_COMMIT();

    for (int kc = 0; kc < 32; kc++) {
        storeA();
        if (kc < 31) { cpB(kc + 1, (kc + 1) & 1); CP_COMMIT(); CP_WAIT1(); }
        else         { CP_WAIT0(); }
        __syncthreads();                     // A stores + B(kc) visible
        if (kc < 31) ldgA(kc + 1);           // overlaps compute

        const uint32_t bbase = sB0 + (uint32_t)(kc & 1) * 10240u;
#pragma unroll
        for (int s = 0; s < 2; s++) {
            const uint32_t colk = (uint32_t)s * 32u;
            uint32_t ah[2][4];
#pragma unroll
            for (int mt = 0; mt < 2; mt++) ldsm4(ah[mt], aSm + aoff[mt] + colk);
#pragma unroll
            for (int bp = 0; bp < 4; bp++) {
                uint32_t bh[4];
                ldsm4(bh, bbase + boff[bp] + colk);
#pragma unroll
                for (int mt = 0; mt < 2; mt++) {
                    mma16816h(acc[mt][2 * bp],     ah[mt], bh[0], bh[2]);
                    mma16816h(acc[mt][2 * bp + 1], ah[mt], bh[1], bh[3]);
                }
            }
        }
        __syncthreads();                     // reads done before next storeA
    }

    // ---- register epilogue (proven) ----
    const int bh2 = b0 * 8 + h;
#pragma unroll
    for (int mt = 0; mt < 2; mt++)
#pragma unroll
        for (int nf = 0; nf < 8; nf++) {
            const int c = wn * 64 + nf * 8 + 2 * (lane & 3);
            acc[mt][nf][0] = celu_f(acc[mt][nf][0] + sbias[c]);
            acc[mt][nf][1] = celu_f(acc[mt][nf][1] + sbias[c + 1]);
            acc[mt][nf][2] = celu_f(acc[mt][nf][2] + sbias[c]);
            acc[mt][nf][3] = celu_f(acc[mt][nf][3] + sbias[c + 1]);
        }

#pragma unroll
    for (int mt = 0; mt < 2; mt++) {
        float sA2 = 0.f, s2A = 0.f, sBv = 0.f, s2B = 0.f;
#pragma unroll
        for (int nf = 0; nf < 8; nf++) {
            sA2 += acc[mt][nf][0] + acc[mt][nf][1];
            s2A = fmaf(acc[mt][nf][0], acc[mt][nf][0], fmaf(acc[mt][nf][1], acc[mt][nf][1], s2A));
            sBv += acc[mt][nf][2] + acc[mt][nf][3];
            s2B = fmaf(acc[mt][nf][2], acc[mt][nf][2], fmaf(acc[mt][nf][3], acc[mt][nf][3], s2B));
        }
        sA2 = quad2(sA2); s2A = quad2(s2A); sBv = quad2(sBv); s2B = quad2(s2B);
        if ((lane & 3) == 0) {
            const int R = wm * 32 + mt * 16 + (lane >> 2);
            psum[R][wn] = sA2;      psum2[R][wn] = s2A;
            psum[R + 8][wn] = sBv;  psum2[R + 8][wn] = s2B;
        }
    }
    __syncthreads();

    float mu_[2][2], rs_[2][2];
#pragma unroll
    for (int mt = 0; mt < 2; mt++)
#pragma unroll
        for (int hf = 0; hf < 2; hf++) {
            const int R = wm * 32 + mt * 16 + (lane >> 2) + 8 * hf;
            const float S  = psum[R][0] + psum[R][1];
            const float S2 = psum2[R][0] + psum2[R][1];
            const float mu = S * (1.f / 128.f);
            mu_[mt][hf] = mu;
            rs_[mt][hf] = rsqrtf(S2 * (1.f / 128.f) - mu * mu + GNEPS);
        }

    if (mode == 0) {
#pragma unroll
        for (int mt = 0; mt < 2; mt++) {
            float dpA = 0.f, k2A = 0.f, dpB = 0.f, k2B = 0.f;
#pragma unroll
            for (int nf = 0; nf < 8; nf++) {
                const int c = wn * 64 + nf * 8 + 2 * (lane & 3);
                float v0 = (acc[mt][nf][0] - mu_[mt][0]) * rs_[mt][0] * sg[c]     + sbeta[c];
                float v1 = (acc[mt][nf][1] - mu_[mt][0]) * rs_[mt][0] * sg[c + 1] + sbeta[c + 1];
                float v2 = (acc[mt][nf][2] - mu_[mt][1]) * rs_[mt][1] * sg[c]     + sbeta[c];
                float v3 = (acc[mt][nf][3] - mu_[mt][1]) * rs_[mt][1] * sg[c + 1] + sbeta[c + 1];
                dpA = fmaf(v0, sq[c], fmaf(v1, sq[c + 1], dpA));
                k2A = fmaf(v0, v0, fmaf(v1, v1, k2A));
                dpB = fmaf(v2, sq[c], fmaf(v3, sq[c + 1], dpB));
                k2B = fmaf(v2, v2, fmaf(v3, v3, k2B));
            }
            dpA = quad2(dpA); k2A = quad2(k2A); dpB = quad2(dpB); k2B = quad2(k2B);
            if ((lane & 3) == 0) {
                const int R = wm * 32 + mt * 16 + (lane >> 2);
                pdot[R][wn] = dpA;      pk2[R][wn] = k2A;
                pdot[R + 8][wn] = dpB;  pk2[R + 8][wn] = k2B;
            }
        }
        __syncthreads();
        if (wn == 0 && (lane & 3) == 0) {
#pragma unroll
            for (int mt = 0; mt < 2; mt++)
#pragma unroll
                for (int hf = 0; hf < 2; hf++) {
                    const int R = wm * 32 + mt * 16 + (lane >> 2) + 8 * hf;
                    const int m = (tm * 128 + R) & 1023;
                    g_dotb[bh2 * 1024 + m] = pdot[R][0] + pdot[R][1];
                    g_knb[bh2 * 1024 + m]  = sqrtf(pk2[R][0] + pk2[R][1]);
                }
        }
    } else {
#pragma unroll
        for (int mt = 0; mt < 2; mt++)
#pragma unroll
            for (int hf = 0; hf < 2; hf++) {
                const int R = wm * 32 + mt * 16 + (lane >> 2) + 8 * hf;
                const int m = (tm * 128 + R) & 1023;
                __half* dst = g_v2h + ((size_t)bh2 * 1024 + m) * 128;
                const float mu = mu_[mt][hf], rstd = rs_[mt][hf];
#pragma unroll
                for (int nf = 0; nf < 8; nf++) {
                    const int c = wn * 64 + nf * 8 + 2 * (lane & 3);
                    const float v0 = (acc[mt][nf][2 * hf]     - mu) * rstd * sg[c]     + sbeta[c];
                    const float v1 = (acc[mt][nf][2 * hf + 1] - mu) * rstd * sg[c + 1] + sbeta[c + 1];
                    *(__half2*)(dst + c) = __floats2half2_rn(v0, v1);
                }
            }
    }
}

// ---------------- attention / pooling / output (256 threads) -----------------
__device__ __forceinline__ float bsum256(float v, float* sh) {
#pragma unroll
    for (int o = 16; o; o >>= 1) v += __shfl_xor_sync(0xffffffffu, v, o);
    if ((threadIdx.x & 31) == 0) sh[threadIdx.x >> 5] = v;
    __syncthreads();
    v = (sh[0] + sh[1]) + (sh[2] + sh[3]) + ((sh[4] + sh[5]) + (sh[6] + sh[7]));
    __syncthreads();
    return v;
}
__device__ __forceinline__ float bmax256(float v, float* sh) {
#pragma unroll
    for (int o = 16; o; o >>= 1) v = fmaxf(v, __shfl_xor_sync(0xffffffffu, v, o));
    if ((threadIdx.x & 31) == 0) sh[threadIdx.x >> 5] = v;
    __syncthreads();
    v = fmaxf(fmaxf(fmaxf(sh[0], sh[1]), fmaxf(sh[2], sh[3])),
              fmaxf(fmaxf(sh[4], sh[5]), fmaxf(sh[6], sh[7])));
    __syncthreads();
    return v;
}

__global__ __launch_bounds__(256) void attn_kernel(
    const float* __restrict__ mask,
    const float* __restrict__ W1,  const float* __restrict__ b1,
    const float* __restrict__ Wl,  const float* __restrict__ bl,
    const float* __restrict__ Wl2, const float* __restrict__ bl2,
    float* __restrict__ out)
{
    __shared__ float qdir[128], u[64], b1s[64], wls[64], pool[64];
    __shared__ float cosv[1024], aspv[1024], maskv[1024];
    __shared__ float pp[4][64];
    __shared__ float vo[4][128];
    __shared__ float sh[8];

    const int bh  = blockIdx.x;
    const int b   = bh >> 3;
    const int tid = threadIdx.x;

    const float qv = (tid < 128) ? g_qbuf[bh * 128 + tid] : 0.f;
    const float qn = sqrtf(bsum256(qv * qv, sh));
    if (tid < 128) qdir[tid] = qv / fmaxf(qn, 1e-12f);
    if (tid < 64) { b1s[tid] = b1[tid]; wls[tid] = Wl[tid]; }
    __syncthreads();

    if (tid < 64) {
        float a = 0.f;
#pragma unroll 4
        for (int d = 0; d < 128; d++) a = fmaf(qdir[d], W1[d * 64 + tid], a);
        u[tid] = a;
    }
    __syncthreads();

    const float qnc = fmaxf(qn, 1e-8f);
    const float bl0 = bl[0];

    float lmax = -1e30f, msum = 0.f;
#pragma unroll
    for (int mi = 0; mi < 4; mi++) {
        const int m = tid + mi * 256;
        const float kn = g_knb[bh * 1024 + m];
        const float cs = g_dotb[bh * 1024 + m] / (qnc * fmaxf(kn, 1e-8f));
        cosv[m] = cs;
        const float mk = mask[b * 1024 + m];
        maskv[m] = mk;
        msum += mk;
        float lg = bl0;
#pragma unroll 8
        for (int j = 0; j < 64; j++)
            lg = fmaf(fmaxf(fmaf(cs, u[j], b1s[j]), 0.f), wls[j], lg);
        if (mk == 0.f) lg = -1e9f;
        aspv[m] = lg;
        lmax = fmaxf(lmax, lg);
    }
    lmax = bmax256(lmax, sh);
    msum = bsum256(msum, sh);

    float esum = 0.f;
#pragma unroll
    for (int mi = 0; mi < 4; mi++) {
        const int m = tid + mi * 256;
        const float e = expf(aspv[m] - lmax);
        aspv[m] = e;
        esum += e;
    }
    esum = bsum256(esum, sh);
    const float inv = 1.f / esum;
    __syncthreads();

    {
        const int j = tid & 63, qtr = tid >> 6;
        const float uj = u[j], bj = b1s[j];
        float p = 0.f;
        const int m0 = qtr * 256;
#pragma unroll 8
        for (int m = m0; m < m0 + 256; m++)
            p = fmaf(fmaxf(fmaf(cosv[m], uj, bj), 0.f), maskv[m], p);
        pp[qtr][j] = p;
    }
    __syncthreads();
    if (tid < 64)
        pool[tid] = (pp[0][tid] + pp[1][tid] + pp[2][tid] + pp[3][tid]) / msum;
    __syncthreads();

    {
        const int cc = (tid & 63) * 2, qtr = tid >> 6;
        const __half2* vb = (const __half2*)(g_v2h + (size_t)bh * 131072
                                             + (size_t)(qtr * 256) * 128 + cc);
        const float* av = aspv + qtr * 256;
        float ax = 0.f, ay = 0.f;
#pragma unroll 8
        for (int m = 0; m < 256; m++) {
            const float2 hv = __half22float2(vb[(size_t)m * 64]);
            const float w = av[m];
            ax = fmaf(w, hv.x, ax);
            ay = fmaf(w, hv.y, ay);
        }
        vo[qtr][cc] = ax;
        vo[qtr][cc + 1] = ay;
    }
    __syncthreads();

    if (tid < 128) {
        float a2 = bl2[tid];
#pragma unroll 8
        for (int j = 0; j < 64; j++) a2 = fmaf(pool[j], Wl2[j * 128 + tid], a2);
        const float ach = 1.f / (1.f + expf(-a2));
        const float v2o = (vo[0][tid] + vo[1][tid] + vo[2][tid] + vo[3][tid]) * inv;
        out[bh * 128 + tid] = g_v1buf[bh * 128 + tid] * v2o * ach;
    }
}

// ---------------- launch ------------------------------------------------------
extern "C" void kernel_launch(void* const* d_in, const int* in_sizes, int n_in,
                              void* d_out, int out_size) {
    const float* query   = (const float*)d_in[0];
    const float* key     = (const float*)d_in[1];
    const float* mask    = (const float*)d_in[2];
    const float* value1  = (const float*)d_in[3];
    const float* value2  = (const float*)d_in[4];
    const float* W_q     = (const float*)d_in[5];
    const float* b_q     = (const float*)d_in[6];
    const float* g_q     = (const float*)d_in[7];
    const float* beta_q  = (const float*)d_in[8];
    const float* W_k     = (const float*)d_in[9];
    const float* b_k     = (const float*)d_in[10];
    const float* g_k     = (const float*)d_in[11];
    const float* beta_k  = (const float*)d_in[12];
    const float* W_v1    = (const float*)d_in[13];
    const float* b_v1    = (const float*)d_in[14];
    const float* g_v1    = (const float*)d_in[15];
    const float* beta_v1 = (const float*)d_in[16];
    const float* W_v2    = (const float*)d_in[17];
    const float* b_v2    = (const float*)d_in[18];
    const float* g_v2    = (const float*)d_in[19];
    const float* beta_v2 = (const float*)d_in[20];
    const float* W1      = (const float*)d_in[21];
    const float* b1      = (const float*)d_in[22];
    const float* Wl      = (const float*)d_in[23];
    const float* bl      = (const float*)d_in[24];
    const float* Wl2     = (const float*)d_in[25];
    const float* bl2     = (const float*)d_in[26];
    float* out = (float*)d_out;

    convB_kernel<<<dim3(32, 8, 2), 256>>>(W_k, W_v2);

    small_proj_kernel<<<dim3(512, 2), 512>>>(query,  W_q,  b_q,  g_q,  beta_q,
                                             value1, W_v1, b_v1, g_v1, beta_v1);

    big_mma_kernel<<<dim3(8, 512, 2), 256>>>(key, value2,
                                             b_k,  g_k,  beta_k,
                                             b_v2, g_v2, beta_v2);

    attn_kernel<<<512, 256>>>(mask, W1, b1, Wl, bl, Wl2, bl2, out);
}

// round 16
// speedup vs baseline: 1.5306x; 1.0006x over previous
#include <cuda_runtime.h>
#include <cuda_bf16.h>
#include <cuda_fp16.h>
#include <math.h>
#include <stdint.h>

#define ALPHA 1.3f
#define GNEPS 1e-5f
// B=64, M=1024, D=1024, H=8, HD=128

// ---------------- scratch (__device__ globals) -------------------------------
__device__ float g_qbuf[64 * 1024];
__device__ float g_v1buf[64 * 1024];
__device__ float g_dotb[64 * 8 * 1024];
__device__ float g_knb[64 * 8 * 1024];
__device__ __half g_v2h[67108864];             // v2 projected fp16

// Pre-converted W^T tiles (fp16): [mode][ (h*32+kc)*128 + n ]*40 + k  (K=32 chunks, pad 40)
__device__ __half g_Bf[2][2621440];

__device__ __forceinline__ float celu_f(float x) {
    return x > 0.f ? x : ALPHA * expm1f(x * (1.0f / ALPHA));
}

// ---------------- PTX helpers ------------------------------------------------
__device__ __forceinline__ uint32_t smem_u32(const void* p) {
    return (uint32_t)__cvta_generic_to_shared(p);
}
__device__ __forceinline__ void cp16(uint32_t dst, const void* src) {
    asm volatile("cp.async.cg.shared.global [%0], [%1], 16;\n"
                 :: "r"(dst), "l"(__cvta_generic_to_global(src)));
}
#define CP_COMMIT()  asm volatile("cp.async.commit_group;\n" ::: "memory")
#define CP_WAIT1()   asm volatile("cp.async.wait_group 1;\n" ::: "memory")
#define CP_WAIT0()   asm volatile("cp.async.wait_group 0;\n" ::: "memory")

__device__ __forceinline__ void ldsm4(uint32_t* d, uint32_t addr) {
    asm volatile("ldmatrix.sync.aligned.m8n8.x4.shared.b16 {%0,%1,%2,%3}, [%4];"
                 : "=r"(d[0]), "=r"(d[1]), "=r"(d[2]), "=r"(d[3]) : "r"(addr));
}
__device__ __forceinline__ void mma16816h(float* c, const uint32_t* a,
                                          uint32_t b0, uint32_t b1) {
    asm volatile(
        "mma.sync.aligned.m16n8k16.row.col.f32.f16.f16.f32 "
        "{%0,%1,%2,%3}, {%4,%5,%6,%7}, {%8,%9}, {%0,%1,%2,%3};"
        : "+f"(c[0]), "+f"(c[1]), "+f"(c[2]), "+f"(c[3])
        : "r"(a[0]), "r"(a[1]), "r"(a[2]), "r"(a[3]), "r"(b0), "r"(b1));
}
__device__ __forceinline__ float quad2(float v) {
    v += __shfl_xor_sync(0xffffffffu, v, 1);
    v += __shfl_xor_sync(0xffffffffu, v, 2);
    return v;
}
__device__ __forceinline__ uint4 pack8_f16(const float* v) {
    uint4 r;
    __half2 p;
    p = __floats2half2_rn(v[0], v[1]); r.x = *(uint32_t*)&p;
    p = __floats2half2_rn(v[2], v[3]); r.y = *(uint32_t*)&p;
    p = __floats2half2_rn(v[4], v[5]); r.z = *(uint32_t*)&p;
    p = __floats2half2_rn(v[6], v[7]); r.w = *(uint32_t*)&p;
    return r;
}

// ---------------- convB: W -> per-head [n][k32] fp16 padded tiles -------------
// grid (32 kc, 8 head, 2 mode), 256 threads; thread: n = tid&127, kh = (tid>>7)*16
__global__ __launch_bounds__(256) void convB_kernel(
    const float* __restrict__ W_k, const float* __restrict__ W_v2)
{
    const int kc = blockIdx.x, h = blockIdx.y, mode = blockIdx.z, tid = threadIdx.x;
    const float* W = mode ? W_v2 : W_k;
    const int n = tid & 127;
    const int kh = (tid >> 7) * 16;
    float vals[16];
#pragma unroll
    for (int j = 0; j < 16; j++)
        vals[j] = W[(size_t)(kc * 32 + kh + j) * 1024 + h * 128 + n];
    const size_t base = ((size_t)(h * 32 + kc) * 128 + n) * 40 + kh;
    *(uint4*)&g_Bf[mode][base]     = pack8_f16(vals);
    *(uint4*)&g_Bf[mode][base + 8] = pack8_f16(vals + 8);
}

// ---------------- small projections: q + v1 merged (grid.y = 2) --------------
__global__ __launch_bounds__(512) void small_proj_kernel(
    const float* __restrict__ Xq, const float* __restrict__ Wq,
    const float* __restrict__ bq, const float* __restrict__ gq, const float* __restrict__ betq,
    const float* __restrict__ Xv, const float* __restrict__ Wv,
    const float* __restrict__ bv, const float* __restrict__ gv, const float* __restrict__ betv)
{
    __shared__ float xs[1024];
    __shared__ float part[4][128];
    __shared__ float sh[16];
    const int row = blockIdx.x >> 3;
    const int h   = blockIdx.x & 7;
    const int dst = blockIdx.y;
    const int tid = threadIdx.x;
    const int c   = tid & 127;
    const int kq  = tid >> 7;

    const float* X     = dst ? Xv   : Xq;
    const float* W     = dst ? Wv   : Wq;
    const float* bias  = dst ? bv   : bq;
    const float* gw    = dst ? gv   : gq;
    const float* betaw = dst ? betv : betq;

    if (tid < 256)
        ((float4*)xs)[tid] = ((const float4*)(X + (size_t)row * 1024))[tid];
    __syncthreads();

    const int col = h * 128 + c;
    const float* Wp = W + (size_t)(kq * 256) * 1024 + col;
    const float* xp = xs + kq * 256;
    float a = 0.f;
#pragma unroll 16
    for (int k = 0; k < 256; k++) a = fmaf(xp[k], Wp[(size_t)k * 1024], a);
    part[kq][c] = a;
    __syncthreads();

    float acc = 0.f;
    if (tid < 128)
        acc = celu_f(part[0][c] + part[1][c] + part[2][c] + part[3][c] + bias[col]);

    float s = acc, s2 = acc * acc;
#pragma unroll
    for (int o = 16; o; o >>= 1) {
        s  += __shfl_xor_sync(0xffffffffu, s,  o);
        s2 += __shfl_xor_sync(0xffffffffu, s2, o);
    }
    if ((tid & 31) == 0) { sh[tid >> 5] = s; sh[(tid >> 5) + 8] = s2; }
    __syncthreads();
    if (tid < 128) {
        s  = sh[0] + sh[1] + sh[2]  + sh[3];
        s2 = sh[8] + sh[9] + sh[10] + sh[11];
        const float mu   = s * (1.f / 128.f);
        const float rstd = rsqrtf(s2 * (1.f / 128.f) - mu * mu + GNEPS);
        const float v = (acc - mu) * rstd * gw[col] + betaw[col];
        if (dst == 0) g_qbuf[row * 1024 + col] = v;
        else          g_v1buf[row * 1024 + col] = v;
    }
}

// ---------------- merged tensor-core big projection GEMM ---------------------
// grid (8 heads, 512 row-tiles, 2 modes), 256 thr = 8 warps (4M x 2N).
// Single-pass fp16, K-chunk 32 (32 iterations, half the barriers of K16).
__global__ __launch_bounds__(256, 2) void big_mma_kernel(
    const float* __restrict__ key,  const float* __restrict__ value2,
    const float* __restrict__ b_k,  const float* __restrict__ g_k,  const float* __restrict__ beta_k,
    const float* __restrict__ b_v,  const float* __restrict__ g_v,  const float* __restrict__ beta_v)
{
    __shared__ __align__(16) __half sA[128][40];       // 10KB
    __shared__ __align__(16) __half sB[2][128][40];    // 20KB
    __shared__ float sbias[128], sg[128], sbeta[128], sq[128];
    __shared__ float psum[128][2], psum2[128][2];
    __shared__ float pdot[128][2], pk2[128][2];

    const int h    = blockIdx.x;
    const int tm   = blockIdx.y;
    const int mode = blockIdx.z;
    const int tid  = threadIdx.x;
    const int lane = tid & 31;
    const int warp = tid >> 5;
    const int wm   = warp >> 1;
    const int wn   = warp & 1;
    const int col0 = h * 128;
    const int b0   = tm >> 3;

    const float* A     = mode ? value2 : key;
    const float* bias  = mode ? b_v    : b_k;
    const float* gw    = mode ? g_v    : g_k;
    const float* betaw = mode ? beta_v : beta_k;

    if (tid < 128) {
        sbias[tid] = bias[col0 + tid];
        sg[tid]    = gw[col0 + tid];
        sbeta[tid] = betaw[col0 + tid];
        sq[tid]    = (mode == 0) ? g_qbuf[b0 * 1024 + col0 + tid] : 0.f;
    }

    // A: thread -> (row, 16-float half of k32)
    const int ar = tid >> 1;
    const int ak = (tid & 1) * 16;
    const float* Abase = A + (size_t)(tm * 128 + ar) * 1024 + ak;

    float pf[16];
    auto ldgA = [&](int kc) {
        const float4* p = (const float4*)(Abase + kc * 32);
        *(float4*)&pf[0]  = p[0];
        *(float4*)&pf[4]  = p[1];
        *(float4*)&pf[8]  = p[2];
        *(float4*)&pf[12] = p[3];
    };
    const uint32_t aRow = smem_u32(&sA[ar][ak]);
    auto storeA = [&]() {
        *(uint4*)__cvta_shared_to_generic(aRow)       = pack8_f16(pf);
        *(uint4*)__cvta_shared_to_generic(aRow + 16u) = pack8_f16(pf + 8);
    };

    const __half* Bsrc = g_Bf[mode];
    const uint32_t sB0 = smem_u32(&sB[0][0][0]);
    auto cpB = [&](int kc, int stg) {
        const size_t tb = (size_t)(h * 32 + kc) * 5120;    // halves (128*40)
        const uint32_t d = sB0 + (uint32_t)stg * 10240u;
        cp16(d + (uint32_t)tid * 16u,           Bsrc + tb + (size_t)tid * 8);
        cp16(d + (uint32_t)(tid + 256) * 16u,   Bsrc + tb + (size_t)(tid + 256) * 8);
        if (tid < 128)
            cp16(d + (uint32_t)(tid + 512) * 16u, Bsrc + tb + (size_t)(tid + 512) * 8);
    };

    const uint32_t aSm = smem_u32(sA);
    const uint32_t klane = (uint32_t)(((lane >> 4) & 1) * 16);
    uint32_t aoff[2];
#pragma unroll
    for (int mt = 0; mt < 2; mt++) {
        const int r = wm * 32 + mt * 16 + (lane & 7) + 8 * ((lane >> 3) & 1);
        aoff[mt] = (uint32_t)r * 80u + klane;
    }
    uint32_t boff[4];
#pragma unroll
    for (int bp = 0; bp < 4; bp++) {
        const int n = wn * 64 + bp * 16 + (lane & 7) + 8 * ((lane >> 3) & 1);
        boff[bp] = (uint32_t)n * 80u + klane;
    }

    float acc[2][8][4];
#pragma unroll
    for (int mt = 0; mt < 2; mt++)
#pragma unroll
        for (int nf = 0; nf < 8; nf++)
#pragma unroll
            for (int q = 0; q < 4; q++) acc[mt][nf][q] = 0.f;

    ldgA(0);
    cpB(0, 0);
    CP_COMMIT();

    for (int kc = 0; kc < 32; kc++) {
        storeA();
        if (kc < 31) { cpB(kc + 1, (kc + 1) & 1); CP_COMMIT(); CP_WAIT1(); }
        else         { CP_WAIT0(); }
        __syncthreads();                     // A stores + B(kc) visible
        if (kc < 31) ldgA(kc + 1);           // overlaps compute

        const uint32_t bbase = sB0 + (uint32_t)(kc & 1) * 10240u;
#pragma unroll
        for (int s = 0; s < 2; s++) {
            const uint32_t colk = (uint32_t)s * 32u;
            uint32_t ah[2][4];
#pragma unroll
            for (int mt = 0; mt < 2; mt++) ldsm4(ah[mt], aSm + aoff[mt] + colk);
#pragma unroll
            for (int bp = 0; bp < 4; bp++) {
                uint32_t bh[4];
                ldsm4(bh, bbase + boff[bp] + colk);
#pragma unroll
                for (int mt = 0; mt < 2; mt++) {
                    mma16816h(acc[mt][2 * bp],     ah[mt], bh[0], bh[2]);
                    mma16816h(acc[mt][2 * bp + 1], ah[mt], bh[1], bh[3]);
                }
            }
        }
        __syncthreads();                     // reads done before next storeA
    }

    // ---- register epilogue (proven) ----
    const int bh2 = b0 * 8 + h;
#pragma unroll
    for (int mt = 0; mt < 2; mt++)
#pragma unroll
        for (int nf = 0; nf < 8; nf++) {
            const int c = wn * 64 + nf * 8 + 2 * (lane & 3);
            acc[mt][nf][0] = celu_f(acc[mt][nf][0] + sbias[c]);
            acc[mt][nf][1] = celu_f(acc[mt][nf][1] + sbias[c + 1]);
            acc[mt][nf][2] = celu_f(acc[mt][nf][2] + sbias[c]);
            acc[mt][nf][3] = celu_f(acc[mt][nf][3] + sbias[c + 1]);
        }

#pragma unroll
    for (int mt = 0; mt < 2; mt++) {
        float sA2 = 0.f, s2A = 0.f, sBv = 0.f, s2B = 0.f;
#pragma unroll
        for (int nf = 0; nf < 8; nf++) {
            sA2 += acc[mt][nf][0] + acc[mt][nf][1];
            s2A = fmaf(acc[mt][nf][0], acc[mt][nf][0], fmaf(acc[mt][nf][1], acc[mt][nf][1], s2A));
            sBv += acc[mt][nf][2] + acc[mt][nf][3];
            s2B = fmaf(acc[mt][nf][2], acc[mt][nf][2], fmaf(acc[mt][nf][3], acc[mt][nf][3], s2B));
        }
        sA2 = quad2(sA2); s2A = quad2(s2A); sBv = quad2(sBv); s2B = quad2(s2B);
        if ((lane & 3) == 0) {
            const int R = wm * 32 + mt * 16 + (lane >> 2);
            psum[R][wn] = sA2;      psum2[R][wn] = s2A;
            psum[R + 8][wn] = sBv;  psum2[R + 8][wn] = s2B;
        }
    }
    __syncthreads();

    float mu_[2][2], rs_[2][2];
#pragma unroll
    for (int mt = 0; mt < 2; mt++)
#pragma unroll
        for (int hf = 0; hf < 2; hf++) {
            const int R = wm * 32 + mt * 16 + (lane >> 2) + 8 * hf;
            const float S  = psum[R][0] + psum[R][1];
            const float S2 = psum2[R][0] + psum2[R][1];
            const float mu = S * (1.f / 128.f);
            mu_[mt][hf] = mu;
            rs_[mt][hf] = rsqrtf(S2 * (1.f / 128.f) - mu * mu + GNEPS);
        }

    if (mode == 0) {
#pragma unroll
        for (int mt = 0; mt < 2; mt++) {
            float dpA = 0.f, k2A = 0.f, dpB = 0.f, k2B = 0.f;
#pragma unroll
            for (int nf = 0; nf < 8; nf++) {
                const int c = wn * 64 + nf * 8 + 2 * (lane & 3);
                float v0 = (acc[mt][nf][0] - mu_[mt][0]) * rs_[mt][0] * sg[c]     + sbeta[c];
                float v1 = (acc[mt][nf][1] - mu_[mt][0]) * rs_[mt][0] * sg[c + 1] + sbeta[c + 1];
                float v2 = (acc[mt][nf][2] - mu_[mt][1]) * rs_[mt][1] * sg[c]     + sbeta[c];
                float v3 = (acc[mt][nf][3] - mu_[mt][1]) * rs_[mt][1] * sg[c + 1] + sbeta[c + 1];
                dpA = fmaf(v0, sq[c], fmaf(v1, sq[c + 1], dpA));
                k2A = fmaf(v0, v0, fmaf(v1, v1, k2A));
                dpB = fmaf(v2, sq[c], fmaf(v3, sq[c + 1], dpB));
                k2B = fmaf(v2, v2, fmaf(v3, v3, k2B));
            }
            dpA = quad2(dpA); k2A = quad2(k2A); dpB = quad2(dpB); k2B = quad2(k2B);
            if ((lane & 3) == 0) {
                const int R = wm * 32 + mt * 16 + (lane >> 2);
                pdot[R][wn] = dpA;      pk2[R][wn] = k2A;
                pdot[R + 8][wn] = dpB;  pk2[R + 8][wn] = k2B;
            }
        }
        __syncthreads();
        if (wn == 0 && (lane & 3) == 0) {
#pragma unroll
            for (int mt = 0; mt < 2; mt++)
#pragma unroll
                for (int hf = 0; hf < 2; hf++) {
                    const int R = wm * 32 + mt * 16 + (lane >> 2) + 8 * hf;
                    const int m = (tm * 128 + R) & 1023;
                    g_dotb[bh2 * 1024 + m] = pdot[R][0] + pdot[R][1];
                    g_knb[bh2 * 1024 + m]  = sqrtf(pk2[R][0] + pk2[R][1]);
                }
        }
    } else {
#pragma unroll
        for (int mt = 0; mt < 2; mt++)
#pragma unroll
            for (int hf = 0; hf < 2; hf++) {
                const int R = wm * 32 + mt * 16 + (lane >> 2) + 8 * hf;
                const int m = (tm * 128 + R) & 1023;
                __half* dst = g_v2h + ((size_t)bh2 * 1024 + m) * 128;
                const float mu = mu_[mt][hf], rstd = rs_[mt][hf];
#pragma unroll
                for (int nf = 0; nf < 8; nf++) {
                    const int c = wn * 64 + nf * 8 + 2 * (lane & 3);
                    const float v0 = (acc[mt][nf][2 * hf]     - mu) * rstd * sg[c]     + sbeta[c];
                    const float v1 = (acc[mt][nf][2 * hf + 1] - mu) * rstd * sg[c + 1] + sbeta[c + 1];
                    *(__half2*)(dst + c) = __floats2half2_rn(v0, v1);
                }
            }
    }
}

// ---------------- attention / pooling / output (256 threads) -----------------
__device__ __forceinline__ float bsum256(float v, float* sh) {
#pragma unroll
    for (int o = 16; o; o >>= 1) v += __shfl_xor_sync(0xffffffffu, v, o);
    if ((threadIdx.x & 31) == 0) sh[threadIdx.x >> 5] = v;
    __syncthreads();
    v = (sh[0] + sh[1]) + (sh[2] + sh[3]) + ((sh[4] + sh[5]) + (sh[6] + sh[7]));
    __syncthreads();
    return v;
}
__device__ __forceinline__ float bmax256(float v, float* sh) {
#pragma unroll
    for (int o = 16; o; o >>= 1) v = fmaxf(v, __shfl_xor_sync(0xffffffffu, v, o));
    if ((threadIdx.x & 31) == 0) sh[threadIdx.x >> 5] = v;
    __syncthreads();
    v = fmaxf(fmaxf(fmaxf(sh[0], sh[1]), fmaxf(sh[2], sh[3])),
              fmaxf(fmaxf(sh[4], sh[5]), fmaxf(sh[6], sh[7])));
    __syncthreads();
    return v;
}

__global__ __launch_bounds__(256) void attn_kernel(
    const float* __restrict__ mask,
    const float* __restrict__ W1,  const float* __restrict__ b1,
    const float* __restrict__ Wl,  const float* __restrict__ bl,
    const float* __restrict__ Wl2, const float* __restrict__ bl2,
    float* __restrict__ out)
{
    __shared__ float qdir[128], u[64], b1s[64], wls[64], pool[64];
    __shared__ float cosv[1024], aspv[1024], maskv[1024];
    __shared__ float pp[4][64];
    __shared__ float vo[4][128];
    __shared__ float sh[8];

    const int bh  = blockIdx.x;
    const int b   = bh >> 3;
    const int tid = threadIdx.x;

    const float qv = (tid < 128) ? g_qbuf[bh * 128 + tid] : 0.f;
    const float qn = sqrtf(bsum256(qv * qv, sh));
    if (tid < 128) qdir[tid] = qv / fmaxf(qn, 1e-12f);
    if (tid < 64) { b1s[tid] = b1[tid]; wls[tid] = Wl[tid]; }
    __syncthreads();

    if (tid < 64) {
        float a = 0.f;
#pragma unroll 4
        for (int d = 0; d < 128; d++) a = fmaf(qdir[d], W1[d * 64 + tid], a);
        u[tid] = a;
    }
    __syncthreads();

    const float qnc = fmaxf(qn, 1e-8f);
    const float bl0 = bl[0];

    float lmax = -1e30f, msum = 0.f;
#pragma unroll
    for (int mi = 0; mi < 4; mi++) {
        const int m = tid + mi * 256;
        const float kn = g_knb[bh * 1024 + m];
        const float cs = g_dotb[bh * 1024 + m] / (qnc * fmaxf(kn, 1e-8f));
        cosv[m] = cs;
        const float mk = mask[b * 1024 + m];
        maskv[m] = mk;
        msum += mk;
        float lg = bl0;
#pragma unroll 8
        for (int j = 0; j < 64; j++)
            lg = fmaf(fmaxf(fmaf(cs, u[j], b1s[j]), 0.f), wls[j], lg);
        if (mk == 0.f) lg = -1e9f;
        aspv[m] = lg;
        lmax = fmaxf(lmax, lg);
    }
    lmax = bmax256(lmax, sh);
    msum = bsum256(msum, sh);

    float esum = 0.f;
#pragma unroll
    for (int mi = 0; mi < 4; mi++) {
        const int m = tid + mi * 256;
        const float e = expf(aspv[m] - lmax);
        aspv[m] = e;
        esum += e;
    }
    esum = bsum256(esum, sh);
    const float inv = 1.f / esum;
    __syncthreads();

    {
        const int j = tid & 63, qtr = tid >> 6;
        const float uj = u[j], bj = b1s[j];
        float p = 0.f;
        const int m0 = qtr * 256;
#pragma unroll 8
        for (int m = m0; m < m0 + 256; m++)
            p = fmaf(fmaxf(fmaf(cosv[m], uj, bj), 0.f), maskv[m], p);
        pp[qtr][j] = p;
    }
    __syncthreads();
    if (tid < 64)
        pool[tid] = (pp[0][tid] + pp[1][tid] + pp[2][tid] + pp[3][tid]) / msum;
    __syncthreads();

    {
        const int cc = (tid & 63) * 2, qtr = tid >> 6;
        const __half2* vb = (const __half2*)(g_v2h + (size_t)bh * 131072
                                             + (size_t)(qtr * 256) * 128 + cc);
        const float* av = aspv + qtr * 256;
        float ax = 0.f, ay = 0.f;
#pragma unroll 8
        for (int m = 0; m < 256; m++) {
            const float2 hv = __half22float2(vb[(size_t)m * 64]);
            const float w = av[m];
            ax = fmaf(w, hv.x, ax);
            ay = fmaf(w, hv.y, ay);
        }
        vo[qtr][cc] = ax;
        vo[qtr][cc + 1] = ay;
    }
    __syncthreads();

    if (tid < 128) {
        float a2 = bl2[tid];
#pragma unroll 8
        for (int j = 0; j < 64; j++) a2 = fmaf(pool[j], Wl2[j * 128 + tid], a2);
        const float ach = 1.f / (1.f + expf(-a2));
        const float v2o = (vo[0][tid] + vo[1][tid] + vo[2][tid] + vo[3][tid]) * inv;
        out[bh * 128 + tid] = g_v1buf[bh * 128 + tid] * v2o * ach;
    }
}

// ---------------- launch ------------------------------------------------------
extern "C" void kernel_launch(void* const* d_in, const int* in_sizes, int n_in,
                              void* d_out, int out_size) {
    const float* query   = (const float*)d_in[0];
    const float* key     = (const float*)d_in[1];
    const float* mask    = (const float*)d_in[2];
    const float* value1  = (const float*)d_in[3];
    const float* value2  = (const float*)d_in[4];
    const float* W_q     = (const float*)d_in[5];
    const float* b_q     = (const float*)d_in[6];
    const float* g_q     = (const float*)d_in[7];
    const float* beta_q  = (const float*)d_in[8];
    const float* W_k     = (const float*)d_in[9];
    const float* b_k     = (const float*)d_in[10];
    const float* g_k     = (const float*)d_in[11];
    const float* beta_k  = (const float*)d_in[12];
    const float* W_v1    = (const float*)d_in[13];
    const float* b_v1    = (const float*)d_in[14];
    const float* g_v1    = (const float*)d_in[15];
    const float* beta_v1 = (const float*)d_in[16];
    const float* W_v2    = (const float*)d_in[17];
    const float* b_v2    = (const float*)d_in[18];
    const float* g_v2    = (const float*)d_in[19];
    const float* beta_v2 = (const float*)d_in[20];
    const float* W1      = (const float*)d_in[21];
    const float* b1      = (const float*)d_in[22];
    const float* Wl      = (const float*)d_in[23];
    const float* bl      = (const float*)d_in[24];
    const float* Wl2     = (const float*)d_in[25];
    const float* bl2     = (const float*)d_in[26];
    float* out = (float*)d_out;

    convB_kernel<<<dim3(32, 8, 2), 256>>>(W_k, W_v2);

    small_proj_kernel<<<dim3(512, 2), 512>>>(query,  W_q,  b_q,  g_q,  beta_q,
                                             value1, W_v1, b_v1, g_v1, beta_v1);

    big_mma_kernel<<<dim3(8, 512, 2), 256>>>(key, value2,
                                             b_k,  g_k,  beta_k,
                                             b_v2, g_v2, beta_v2);

    attn_kernel<<<512, 256>>>(mask, W1, b1, Wl, bl, Wl2, bl2, out);
}